// round 3
// baseline (speedup 1.0000x reference)
#include <cuda_runtime.h>
#include <math.h>

// Problem dims
#define B_   64
#define N_   256
#define D_   1024
#define E_   8
#define ET_  4
#define HT_  1024
#define HC_  4096
#define HM_  4096
#define BND  (B_*N_*D_)   // 16777216

typedef unsigned long long u64;

// ---------------- device scratch (allocation-free: __device__ globals) ------
__device__ float g_h[BND];                 // 64 MB: modulated LN output / h2
__device__ float g_mix[BND];               // 64 MB: mixer accumulation
__device__ float g_hid[134217728];         // 512 MB: per-(sample,slot) hidden (1M floats each), reused by MLP hid
__device__ float g_mod[B_*6144];           // adaLN modulation (pre-bias; bias added at consumption)
__device__ float g_rin[B_*D_];             // mean-pooled router input
__device__ float g_probs[B_*E_];
__device__ float g_combine[B_*E_];
__device__ int   g_top1[B_];
__device__ unsigned char g_slot[B_*E_];    // 0/1 = which scratch slot, 255 = not selected

// ---------------- math helpers ----------------------------------------------
__device__ __forceinline__ float gelu_f(float x){
    const float c0 = 0.7978845608028654f;   // sqrt(2/pi)
    float x3 = x*x*x;
    float t = tanhf(c0*(x + 0.044715f*x3));
    return 0.5f*x*(1.0f+t);
}
__device__ __forceinline__ float silu_f(float x){
    return x / (1.0f + __expf(-x));
}

// packed fp32x2 FMA (Blackwell; ptxas never auto-emits this)
#define FMA2(c,a,b) asm("fma.rn.f32x2 %0, %1, %2, %3;" : "=l"(c) : "l"(a), "l"(b), "l"(c))

__device__ __forceinline__ float lo32(u64 p){ return __uint_as_float((unsigned)p); }
__device__ __forceinline__ float hi32(u64 p){ return __uint_as_float((unsigned)(p>>32)); }

// ---------------- GEMM modes -------------------------------------------------
enum { M_TOK1=0, M_TOK2=1, M_CH1=2, M_CH2=3, M_MLP1=4, M_MLP2=5, M_MOD=6 };

// 128x128x8 register-blocked SGEMM, 256 threads, 8x8 per thread (FFMA2 inner loop).
template<int MODE>
__global__ __launch_bounds__(256) void gemm_tpl(
    const float* __restrict__ Aext,   // c for M_MOD, else unused
    const float* __restrict__ W,
    const float* __restrict__ bias,
    const float* __restrict__ b_ada,  // M_MLP2 only
    float* __restrict__ outp)         // d_out for M_MLP2
{
    constexpr int Ntot = (MODE==M_TOK1)?HT_ : (MODE==M_TOK2)?N_
                       : (MODE==M_CH1)?HC_ : (MODE==M_CH2)?D_
                       : (MODE==M_MLP1)?HM_ : (MODE==M_MLP2)?D_ : 6144;
    constexpr int Ktot = (MODE==M_TOK1)?N_ : (MODE==M_CH2||MODE==M_MLP2)?HC_ : D_;
    constexpr int LDA  = (MODE==M_CH2||MODE==M_MLP2)?4096 : 1024;
    constexpr int LDC  = (MODE==M_TOK1)?1024 : (MODE==M_CH1||MODE==M_MLP1)?4096 : 1;
    constexpr bool AKM = (MODE==M_TOK1);  // A is K-major (h transposed view)

    const int tid = threadIdx.x;
    const int m0 = blockIdx.y * 128;
    const int n0 = blockIdx.x * 128;

    const float* Ap = nullptr;
    const float* We = W;
    const float* be = bias;
    float* Cp = nullptr;
    float* mixp = nullptr;
    float wgt = 0.f;
    int kbeg = 0, kend = Ktot;

    if constexpr (MODE==M_TOK1 || MODE==M_TOK2 || MODE==M_CH1 || MODE==M_CH2) {
        int b = blockIdx.z >> 2;
        int e = blockIdx.z & 3;
        int eg = (MODE==M_CH1 || MODE==M_CH2) ? (ET_ + e) : e;
        unsigned char sl = g_slot[b*E_ + eg];
        if (sl == 255u) return;                 // expert not selected for this sample
        float* hid = g_hid + (size_t)(b*2 + sl) * 1048576u;
        if constexpr (MODE==M_TOK1) {
            Ap = g_h + (size_t)b*N_*D_;         // A[m,k] = h[b][k][m]
            We = W   + (size_t)e*N_*HT_;
            be = bias + e*HT_;
            Cp = hid;                           // (1024 x 1024)
        } else if constexpr (MODE==M_TOK2) {
            Ap = hid;                           // (1024 x 1024) row-major
            We = W   + (size_t)e*HT_*N_;
            be = bias + e*N_;
            mixp = g_mix + (size_t)b*N_*D_;
            wgt = g_combine[b*E_ + eg];
        } else if constexpr (MODE==M_CH1) {
            Ap = g_h + (size_t)b*N_*D_;         // (256 x 1024) row-major
            We = W   + (size_t)e*D_*HC_;
            be = bias + e*HC_;
            Cp = hid;                           // (256 x 4096)
        } else {                                 // M_CH2
            Ap = hid;                           // (256 x 4096) row-major
            We = W   + (size_t)e*HC_*D_;
            be = bias + e*D_;
            mixp = g_mix + (size_t)b*N_*D_;
            wgt = g_combine[b*E_ + eg];
        }
    } else if constexpr (MODE==M_MLP1) {
        Ap = g_h;                                // (16384 x 1024)
        Cp = g_hid;                              // (16384 x 4096)
    } else if constexpr (MODE==M_MLP2) {
        Ap = g_hid;                              // (16384 x 4096)
    } else {                                     // M_MOD: K-split slice
        Ap = Aext;                               // c (64 x 1024), silu applied on load
        kbeg = blockIdx.z * 128;
        kend = kbeg + 128;
    }

    // A tile stored as duplicated pairs {v,v} so FFMA2 needs no per-k packing.
    __shared__ __align__(16) float2 As2[8][130];
    __shared__ __align__(16) float  Bs[8][132];

    u64 acc2[8][4];
    #pragma unroll
    for (int i=0;i<8;i++)
        #pragma unroll
        for (int j=0;j<4;j++) acc2[i][j] = 0ull;

    const int tx = tid & 15, ty = tid >> 4;

    for (int k0 = kbeg; k0 < kend; k0 += 8) {
        // ---- load A tile into As2[k][m] = {a,a} ----
        if constexpr (AKM) {
            #pragma unroll
            for (int j=0;j<4;j++){
                int i = tid + j*256;
                int m = i & 127, kk = i >> 7;
                float v = Ap[(size_t)(k0+kk)*D_ + (m0+m)];
                As2[kk][m] = make_float2(v, v);
            }
        } else {
            #pragma unroll
            for (int j=0;j<2;j++){
                int i = tid + j*256;           // 512 float2 loads cover 128m x 8k
                int m = i >> 2, kp = i & 3;
                float2 v;
                if constexpr (MODE==M_MOD) {
                    int gm = m0 + m;
                    if (gm < B_) {
                        v = *reinterpret_cast<const float2*>(&Ap[gm*D_ + k0 + kp*2]);
                        v.x = silu_f(v.x); v.y = silu_f(v.y);
                    } else v = make_float2(0.f, 0.f);
                } else {
                    v = *reinterpret_cast<const float2*>(&Ap[(size_t)(m0+m)*LDA + k0 + kp*2]);
                }
                As2[kp*2  ][m] = make_float2(v.x, v.x);
                As2[kp*2+1][m] = make_float2(v.y, v.y);
            }
        }
        // ---- load B tile (row-major K x Ntot) ----
        #pragma unroll
        for (int j=0;j<4;j++){
            int i = tid + j*256;
            int kk = i >> 7, n = i & 127;
            Bs[kk][n] = We[(size_t)(k0+kk)*Ntot + (n0+n)];
        }
        __syncthreads();
        #pragma unroll
        for (int kk=0; kk<8; kk++){
            const ulonglong2* ap = reinterpret_cast<const ulonglong2*>(&As2[kk][ty*8]);
            ulonglong2 a01 = ap[0], a23 = ap[1], a45 = ap[2], a67 = ap[3];
            u64 ar[8] = {a01.x, a01.y, a23.x, a23.y, a45.x, a45.y, a67.x, a67.y};
            const ulonglong2* bp = reinterpret_cast<const ulonglong2*>(&Bs[kk][tx*8]);
            ulonglong2 b01 = bp[0], b23 = bp[1];
            u64 br[4] = {b01.x, b01.y, b23.x, b23.y};
            #pragma unroll
            for (int i=0;i<8;i++)
                #pragma unroll
                for (int j=0;j<4;j++)
                    FMA2(acc2[i][j], ar[i], br[j]);
        }
        __syncthreads();
    }

    // ---- epilogue ----
    #pragma unroll
    for (int i=0;i<8;i++){
        int m = m0 + ty*8 + i;
        #pragma unroll
        for (int j=0;j<8;j++){
            int n = n0 + tx*8 + j;
            u64 p = acc2[i][j>>1];
            float v = (j&1) ? hi32(p) : lo32(p);
            if constexpr (MODE==M_TOK1 || MODE==M_CH1 || MODE==M_MLP1) {
                Cp[(size_t)m*LDC + n] = gelu_f(v + be[n]);
            } else if constexpr (MODE==M_TOK2) {
                // C[m=d][n=token] -> mix[b][token][d]
                atomicAdd(&mixp[(size_t)n*D_ + m], wgt*(v + be[n]));
            } else if constexpr (MODE==M_CH2) {
                atomicAdd(&mixp[(size_t)m*D_ + n], wgt*(v + be[n]));
            } else if constexpr (MODE==M_MLP2) {
                int b = m >> 8;
                float gml = g_mod[b*6144 + 5*D_ + n] + b_ada[5*D_ + n];
                size_t o = (size_t)m*D_ + n;
                outp[o] = outp[o] + gml*(v + be[n]);   // x1 (staged in d_out) + g_mlp * mlp_out
            } else { // M_MOD (K-split partial)
                if (m < B_) atomicAdd(&g_mod[m*6144 + n], v);
            }
        }
    }
}

// ---------------- elementwise / routing kernels ------------------------------

__global__ void zero_mod_kernel(){
    int i = blockIdx.x*1024 + threadIdx.x;   // exactly 384*1024 = 64*6144
    g_mod[i] = 0.f;
}

// h = modulate(ln(x), s_msa, sc_msa); mix = 0
__global__ void ew1_kernel(const float* __restrict__ x, const float* __restrict__ b_ada){
    int r = blockIdx.x;            // b*256 + n
    int b = r >> 8;
    int tid = threadIdx.x;
    const float* xr = x + (size_t)r*D_;
    float v[4];
    #pragma unroll
    for (int k=0;k<4;k++) v[k] = xr[tid*4+k];
    float s = v[0]+v[1]+v[2]+v[3];
    float q = v[0]*v[0]+v[1]*v[1]+v[2]*v[2]+v[3]*v[3];
    __shared__ float rs[256], rq[256];
    rs[tid]=s; rq[tid]=q; __syncthreads();
    for (int st=128; st>0; st>>=1){
        if (tid<st){ rs[tid]+=rs[tid+st]; rq[tid]+=rq[tid+st]; }
        __syncthreads();
    }
    float mu  = rs[0]*(1.f/1024.f);
    float var = rq[0]*(1.f/1024.f) - mu*mu;
    float rstd = rsqrtf(var + 1e-6f);
    #pragma unroll
    for (int k=0;k<4;k++){
        int d = tid*4+k;
        float sft = g_mod[b*6144 + d]        + b_ada[d];
        float scl = g_mod[b*6144 + D_ + d]   + b_ada[D_ + d];
        float y = (v[k]-mu)*rstd;
        g_h  [(size_t)r*D_ + d] = y*(1.f+scl) + sft;
        g_mix[(size_t)r*D_ + d] = 0.f;
    }
}

// r_in[b][d] = mean_n h[b][n][d]
__global__ void rin_kernel(){
    int b = blockIdx.y;
    int d = blockIdx.x*256 + threadIdx.x;
    const float* hb = g_h + (size_t)b*N_*D_;
    float s = 0.f;
    for (int n=0;n<N_;n++) s += hb[(size_t)n*D_ + d];
    g_rin[b*D_ + d] = s * (1.f/256.f);
}

__global__ void route_kernel(const float* __restrict__ wr){
    int b = blockIdx.x, tid = threadIdx.x;
    float acc[E_] = {0,0,0,0,0,0,0,0};
    for (int d=tid; d<D_; d+=256){
        float v = g_rin[b*D_ + d];
        #pragma unroll
        for (int e=0;e<E_;e++) acc[e] = fmaf(v, wr[d*E_ + e], acc[e]);
    }
    __shared__ float red[256];
    __shared__ float slog[E_];
    for (int e=0;e<E_;e++){
        red[tid] = acc[e];
        __syncthreads();
        for (int st=128; st>0; st>>=1){
            if (tid<st) red[tid] += red[tid+st];
            __syncthreads();
        }
        if (tid==0) slog[e] = red[0];
        __syncthreads();
    }
    if (tid==0){
        float p[E_];
        float mx = slog[0];
        for (int e=1;e<E_;e++) mx = fmaxf(mx, slog[e]);
        float ssum = 0.f;
        for (int e=0;e<E_;e++){ p[e] = expf(slog[e]-mx); ssum += p[e]; }
        for (int e=0;e<E_;e++){ p[e] /= ssum; g_probs[b*E_+e] = p[e]; }
        int i0 = 0;
        for (int e=1;e<E_;e++) if (p[e] > p[i0]) i0 = e;
        int i1 = (i0==0) ? 1 : 0;
        for (int e=0;e<E_;e++) if (e!=i0 && p[e] > p[i1]) i1 = e;
        float t = p[i0] + p[i1];
        for (int e=0;e<E_;e++){ g_combine[b*E_+e] = 0.f; g_slot[b*E_+e] = 255u; }
        g_combine[b*E_+i0] = p[i0]/t;  g_slot[b*E_+i0] = 0u;
        g_combine[b*E_+i1] = p[i1]/t;  g_slot[b*E_+i1] = 1u;
        g_top1[b] = i0;
    }
}

__global__ void aux_kernel(float* __restrict__ outp, int out_size){
    if (threadIdx.x != 0) return;
    float meanp[E_]; int cnt[E_];
    for (int e=0;e<E_;e++){ meanp[e]=0.f; cnt[e]=0; }
    for (int b=0;b<B_;b++){
        for (int e=0;e<E_;e++) meanp[e] += g_probs[b*E_+e];
        cnt[g_top1[b]]++;
    }
    float aux = 0.f;
    for (int e=0;e<E_;e++) aux += (meanp[e]*(1.f/B_)) * ((float)cnt[e]*(1.f/B_));
    aux *= (float)E_;
    if (out_size > BND) outp[BND] = aux;
}

// x1 = x + g_msa*mix (staged to d_out); h2 = modulate(ln(x1), s_mlp, sc_mlp) -> g_h
__global__ void ew2_kernel(const float* __restrict__ x, const float* __restrict__ b_ada,
                           float* __restrict__ outp){
    int r = blockIdx.x;
    int b = r >> 8;
    int tid = threadIdx.x;
    float v[4];
    #pragma unroll
    for (int k=0;k<4;k++){
        int d = tid*4+k;
        float g = g_mod[b*6144 + 2*D_ + d] + b_ada[2*D_ + d];
        float x1 = x[(size_t)r*D_ + d] + g * g_mix[(size_t)r*D_ + d];
        outp[(size_t)r*D_ + d] = x1;
        v[k] = x1;
    }
    float s = v[0]+v[1]+v[2]+v[3];
    float q = v[0]*v[0]+v[1]*v[1]+v[2]*v[2]+v[3]*v[3];
    __shared__ float rs[256], rq[256];
    rs[tid]=s; rq[tid]=q; __syncthreads();
    for (int st=128; st>0; st>>=1){
        if (tid<st){ rs[tid]+=rs[tid+st]; rq[tid]+=rq[tid+st]; }
        __syncthreads();
    }
    float mu  = rs[0]*(1.f/1024.f);
    float var = rq[0]*(1.f/1024.f) - mu*mu;
    float rstd = rsqrtf(var + 1e-6f);
    #pragma unroll
    for (int k=0;k<4;k++){
        int d = tid*4+k;
        float sft = g_mod[b*6144 + 3*D_ + d] + b_ada[3*D_ + d];
        float scl = g_mod[b*6144 + 4*D_ + d] + b_ada[4*D_ + d];
        float y = (v[k]-mu)*rstd;
        g_h[(size_t)r*D_ + d] = y*(1.f+scl) + sft;
    }
}

// ---------------- launch ------------------------------------------------------
extern "C" void kernel_launch(void* const* d_in, const int* in_sizes, int n_in,
                              void* d_out, int out_size) {
    const float* x        = (const float*)d_in[0];
    const float* c        = (const float*)d_in[1];
    const float* w_ada    = (const float*)d_in[2];
    const float* b_ada    = (const float*)d_in[3];
    const float* w_router = (const float*)d_in[4];
    const float* tm_w1    = (const float*)d_in[5];
    const float* tm_b1    = (const float*)d_in[6];
    const float* tm_w2    = (const float*)d_in[7];
    const float* tm_b2    = (const float*)d_in[8];
    const float* cm_w1    = (const float*)d_in[9];
    const float* cm_b1    = (const float*)d_in[10];
    const float* cm_w2    = (const float*)d_in[11];
    const float* cm_b2    = (const float*)d_in[12];
    const float* mlp_w1   = (const float*)d_in[13];
    const float* mlp_b1   = (const float*)d_in[14];
    const float* mlp_w2   = (const float*)d_in[15];
    const float* mlp_b2   = (const float*)d_in[16];
    float* outp = (float*)d_out;

    // adaLN modulation (K-split, atomic into zeroed g_mod; bias folded at consumers)
    zero_mod_kernel<<<384, 1024>>>();
    gemm_tpl<M_MOD><<<dim3(48,1,8), 256>>>(c, w_ada, nullptr, nullptr, nullptr);

    // LN + modulate; zero mix
    ew1_kernel<<<B_*N_, 256>>>(x, b_ada);

    // routing
    rin_kernel<<<dim3(4, B_), 256>>>();
    route_kernel<<<B_, 256>>>(w_router);
    aux_kernel<<<1, 32>>>(outp, out_size);

    // routed experts (gated per (sample, expert); non-selected blocks exit immediately)
    gemm_tpl<M_TOK1><<<dim3( 8, 8, B_*4), 256>>>(nullptr, tm_w1, tm_b1, nullptr, nullptr);
    gemm_tpl<M_CH1> <<<dim3(32, 2, B_*4), 256>>>(nullptr, cm_w1, cm_b1, nullptr, nullptr);
    gemm_tpl<M_TOK2><<<dim3( 2, 8, B_*4), 256>>>(nullptr, tm_w2, tm_b2, nullptr, nullptr);
    gemm_tpl<M_CH2> <<<dim3( 8, 2, B_*4), 256>>>(nullptr, cm_w2, cm_b2, nullptr, nullptr);

    // residual + second LN/modulate (x1 staged in d_out)
    ew2_kernel<<<B_*N_, 256>>>(x, b_ada, outp);

    // dense MLP, second residual fused into MLP2 epilogue
    gemm_tpl<M_MLP1><<<dim3(32, 128, 1), 256>>>(nullptr, mlp_w1, mlp_b1, nullptr, nullptr);
    gemm_tpl<M_MLP2><<<dim3( 8, 128, 1), 256>>>(nullptr, mlp_w2, mlp_b2, b_ada, outp);
}

// round 5
// speedup vs baseline: 2.6985x; 2.6985x over previous
#include <cuda_runtime.h>
#include <cuda_bf16.h>
#include <math.h>
#include <cstdint>

// Problem dims
#define B_   64
#define N_   256
#define D_   1024
#define E_   8
#define BND  (B_*N_*D_)   // 16777216

// ---------------- weight-transpose offsets (elements) ------------------------
#define OFF_TM1  0u
#define OFF_TM2  1048576u
#define OFF_CM1  2097152u
#define OFF_CM2  18874368u
#define OFF_MLP1 35651584u
#define OFF_MLP2 39845888u
#define WT_TOTAL 44040192u

// ---------------- device scratch (allocation-free: __device__ globals) ------
__device__ float g_hf[BND];                        // fp32 h (router + transpose source)
__device__ float g_mix[BND];                       // mixer accumulation
__device__ __nv_bfloat16 g_ah[BND], g_al[BND];     // h / h2 split  [b][n][d]
__device__ __nv_bfloat16 g_th[BND], g_tl[BND];     // h^T split     [b][d][n]
__device__ __nv_bfloat16 g_eh[134217728], g_el[134217728];  // hidden (expert slots / MLP)
__device__ __nv_bfloat16 g_wh[WT_TOTAL], g_wl[WT_TOTAL];    // transposed split weights [N][K]
__device__ float g_mod[B_*6144];
__device__ float g_rin[B_*D_];
__device__ float g_probs[B_*E_];
__device__ float g_combine[B_*E_];
__device__ int   g_top1[B_];
__device__ unsigned char g_slot[B_*E_];

// ---------------- math helpers ----------------------------------------------
__device__ __forceinline__ float gelu_f(float x){
    const float c0 = 0.7978845608028654f;
    float x3 = x*x*x;
    float t = tanhf(c0*(x + 0.044715f*x3));
    return 0.5f*x*(1.0f+t);
}
__device__ __forceinline__ float silu_f(float x){ return x / (1.0f + __expf(-x)); }

__device__ __forceinline__ void split_bf16(float v, __nv_bfloat16& hi, __nv_bfloat16& lo){
    hi = __float2bfloat16(v);
    lo = __float2bfloat16(v - __bfloat162float(hi));
}

// ---------------- PTX helpers ------------------------------------------------
__device__ __forceinline__ uint32_t smem_u32(const void* p){
    uint32_t a;
    asm("{ .reg .u64 t; cvta.to.shared.u64 t, %1; cvt.u32.u64 %0, t; }" : "=r"(a) : "l"(p));
    return a;
}
__device__ __forceinline__ void cpa16(uint32_t dst, const void* src){
    asm volatile("cp.async.cg.shared.global [%0], [%1], 16;" :: "r"(dst), "l"(src));
}
#define CP_COMMIT()  asm volatile("cp.async.commit_group;" ::: "memory")
#define CP_WAIT(n)   asm volatile("cp.async.wait_group %0;" :: "n"(n) : "memory")

// bf16 m16n8k16 tensor-core MMA, fp32 accum (baseline PTX, no arch-accel features)
#define MMA16816(c, a, b) \
    asm volatile("mma.sync.aligned.m16n8k16.row.col.f32.bf16.bf16.f32 " \
        "{%0,%1,%2,%3}, {%4,%5,%6,%7}, {%8,%9}, {%0,%1,%2,%3};" \
        : "+f"((c)[0]), "+f"((c)[1]), "+f"((c)[2]), "+f"((c)[3]) \
        : "r"((a)[0]), "r"((a)[1]), "r"((a)[2]), "r"((a)[3]), "r"((b)[0]), "r"((b)[1]))

// ---------------- tensor GEMM: D = Ah*Bh^T + Ah*Bl^T + Al*Bh^T ---------------
// 128x128 block tile, BK=32, 256 threads (8 warps, each 32m x 64n).
// smem tiles: 128 rows x 32 bf16, row pitch 80B (conflict-free fragment loads).
enum { T_TOK1=0, T_TOK2=1, T_CH1=2, T_CH2=3, T_MLP1=4, T_MLP2=5 };

#define TILE_B   10240            // 128 * 80
#define STAGE_B  40960            // 4 tiles
#define SMEM_BYTES 81920          // 2 stages

__device__ __forceinline__ void ld_chunk(uint32_t sb, int s,
    const __nv_bfloat16* Ah, const __nv_bfloat16* Al,
    const __nv_bfloat16* Bh, const __nv_bfloat16* Bl,
    int m0, int n0, int k0, int ldk, int tid)
{
    #pragma unroll
    for (int t=0;t<2;t++){
        int j = tid + t*256;
        int r = j >> 2, c16 = j & 3;
        uint32_t d0 = sb + (uint32_t)s*STAGE_B + r*80 + c16*16;
        size_t ga = (size_t)(m0 + r)*ldk + k0 + c16*8;
        size_t gb = (size_t)(n0 + r)*ldk + k0 + c16*8;
        cpa16(d0,             Ah + ga);
        cpa16(d0 +   TILE_B,  Al + ga);
        cpa16(d0 + 2*TILE_B,  Bh + gb);
        cpa16(d0 + 3*TILE_B,  Bl + gb);
    }
    CP_COMMIT();
}

template<int MODE>
__global__ __launch_bounds__(256) void tgemm(const float* __restrict__ bias,
                                             const float* __restrict__ b_ada,
                                             float* __restrict__ outp)
{
    constexpr int Ktot = (MODE==T_TOK1)?256 : (MODE==T_CH2||MODE==T_MLP2)?4096 : 1024;
    constexpr int NC   = Ktot/32;

    const int tid = threadIdx.x;
    const int wid = tid >> 5, lid = tid & 31;
    const int m0 = blockIdx.y*128, n0 = blockIdx.x*128;
    const int warpM = wid & 3, warpN = wid >> 2;
    const int g = lid >> 2, q = lid & 3;

    const __nv_bfloat16 *Ah, *Al, *Bh, *Bl;
    const float* be = bias;
    float wgt = 0.f; float* mixp = nullptr;
    __nv_bfloat16 *Ch = nullptr, *Cl = nullptr;
    constexpr int ldc = (MODE==T_TOK1)?1024 : (MODE==T_CH1||MODE==T_MLP1)?4096 : 1;

    if constexpr (MODE==T_TOK1||MODE==T_TOK2||MODE==T_CH1||MODE==T_CH2){
        int b = blockIdx.z >> 2, e = blockIdx.z & 3;
        int eg = (MODE==T_CH1||MODE==T_CH2) ? 4+e : e;
        unsigned char sl = g_slot[b*E_ + eg];
        if (sl == 255u) return;
        size_t so = (size_t)(b*2 + sl) * 1048576u;
        if constexpr (MODE==T_TOK1){
            Ah = g_th + (size_t)b*262144; Al = g_tl + (size_t)b*262144;
            Bh = g_wh + OFF_TM1 + (size_t)e*262144; Bl = g_wl + OFF_TM1 + (size_t)e*262144;
            be = bias + e*1024; Ch = g_eh + so; Cl = g_el + so;
        } else if constexpr (MODE==T_TOK2){
            Ah = g_eh + so; Al = g_el + so;
            Bh = g_wh + OFF_TM2 + (size_t)e*262144; Bl = g_wl + OFF_TM2 + (size_t)e*262144;
            be = bias + e*256; mixp = g_mix + (size_t)b*262144; wgt = g_combine[b*E_ + eg];
        } else if constexpr (MODE==T_CH1){
            Ah = g_ah + (size_t)b*262144; Al = g_al + (size_t)b*262144;
            Bh = g_wh + OFF_CM1 + (size_t)e*4194304; Bl = g_wl + OFF_CM1 + (size_t)e*4194304;
            be = bias + e*4096; Ch = g_eh + so; Cl = g_el + so;
        } else {
            Ah = g_eh + so; Al = g_el + so;
            Bh = g_wh + OFF_CM2 + (size_t)e*4194304; Bl = g_wl + OFF_CM2 + (size_t)e*4194304;
            be = bias + e*1024; mixp = g_mix + (size_t)b*262144; wgt = g_combine[b*E_ + eg];
        }
    } else if constexpr (MODE==T_MLP1){
        Ah = g_ah; Al = g_al; Bh = g_wh + OFF_MLP1; Bl = g_wl + OFF_MLP1;
        Ch = g_eh; Cl = g_el;
    } else {
        Ah = g_eh; Al = g_el; Bh = g_wh + OFF_MLP2; Bl = g_wl + OFF_MLP2;
    }

    extern __shared__ char smem[];
    const uint32_t sbase = smem_u32(smem);

    float acc[2][8][4];
    #pragma unroll
    for (int i=0;i<2;i++)
        #pragma unroll
        for (int j=0;j<8;j++)
            #pragma unroll
            for (int k=0;k<4;k++) acc[i][j][k] = 0.f;

    ld_chunk(sbase, 0, Ah, Al, Bh, Bl, m0, n0, 0, Ktot, tid);

    for (int c = 0; c < NC; c++){
        int s = c & 1;
        if (c + 1 < NC){
            ld_chunk(sbase, s^1, Ah, Al, Bh, Bl, m0, n0, (c+1)*32, Ktot, tid);
            CP_WAIT(1);
        } else {
            CP_WAIT(0);
        }
        __syncthreads();

        const char* sA  = smem + s*STAGE_B;
        const char* sAl = sA +   TILE_B;
        const char* sB  = sA + 2*TILE_B;
        const char* sBl = sA + 3*TILE_B;

        #pragma unroll
        for (int kk = 0; kk < 32; kk += 16){
            uint32_t afh[2][4], afl[2][4];
            #pragma unroll
            for (int ma=0;ma<2;ma++){
                int r = warpM*32 + ma*16 + g;
                const char* pa = sA  + r*80 + kk*2 + q*4;
                const char* pl = sAl + r*80 + kk*2 + q*4;
                afh[ma][0] = *(const uint32_t*)(pa);
                afh[ma][1] = *(const uint32_t*)(pa + 8*80);
                afh[ma][2] = *(const uint32_t*)(pa + 16);
                afh[ma][3] = *(const uint32_t*)(pa + 8*80 + 16);
                afl[ma][0] = *(const uint32_t*)(pl);
                afl[ma][1] = *(const uint32_t*)(pl + 8*80);
                afl[ma][2] = *(const uint32_t*)(pl + 16);
                afl[ma][3] = *(const uint32_t*)(pl + 8*80 + 16);
            }
            uint32_t bfh[8][2], bfl[8][2];
            #pragma unroll
            for (int nb=0;nb<8;nb++){
                int r = warpN*64 + nb*8 + g;
                const char* pb = sB  + r*80 + kk*2 + q*4;
                const char* pl = sBl + r*80 + kk*2 + q*4;
                bfh[nb][0] = *(const uint32_t*)(pb);
                bfh[nb][1] = *(const uint32_t*)(pb + 16);
                bfl[nb][0] = *(const uint32_t*)(pl);
                bfl[nb][1] = *(const uint32_t*)(pl + 16);
            }
            #pragma unroll
            for (int ma=0;ma<2;ma++)
                #pragma unroll
                for (int nb=0;nb<8;nb++){
                    MMA16816(acc[ma][nb], afh[ma], bfh[nb]);   // Ah*Bh
                    MMA16816(acc[ma][nb], afh[ma], bfl[nb]);   // Ah*Bl
                    MMA16816(acc[ma][nb], afl[ma], bfh[nb]);   // Al*Bh
                }
        }
        __syncthreads();
    }

    // ---- epilogue ----
    #pragma unroll
    for (int ma=0;ma<2;ma++){
        #pragma unroll
        for (int nb=0;nb<8;nb++){
            int r0 = m0 + warpM*32 + ma*16 + g;
            int nc = n0 + warpN*64 + nb*8 + q*2;
            #pragma unroll
            for (int hv=0;hv<2;hv++){            // hv=0: rows r0, hv=1: rows r0+8
                int m = r0 + hv*8;
                #pragma unroll
                for (int jj=0;jj<2;jj++){
                    int n = nc + jj;
                    float v = acc[ma][nb][hv*2+jj] + be[n];
                    if constexpr (MODE==T_TOK1 || MODE==T_CH1 || MODE==T_MLP1){
                        float gg = gelu_f(v);
                        __nv_bfloat16 hi, lo; split_bf16(gg, hi, lo);
                        Ch[(size_t)m*ldc + n] = hi;
                        Cl[(size_t)m*ldc + n] = lo;
                    } else if constexpr (MODE==T_TOK2){
                        atomicAdd(&mixp[(size_t)n*D_ + m], wgt * v);   // m=d, n=token
                    } else if constexpr (MODE==T_CH2){
                        atomicAdd(&mixp[(size_t)m*D_ + n], wgt * v);
                    } else { // MLP2
                        int bb = m >> 8;
                        float gml = g_mod[bb*6144 + 5120 + n] + b_ada[5120 + n];
                        size_t o = (size_t)m*D_ + n;
                        outp[o] = outp[o] + gml * v;
                    }
                }
            }
        }
    }
}

// ---------------- transpose + bf16-split kernels ------------------------------
__global__ void tsplit(const float* __restrict__ src, __nv_bfloat16* __restrict__ dhi,
                       __nv_bfloat16* __restrict__ dlo, int R, int C){
    int z = blockIdx.z;
    src += (size_t)z*R*C; dhi += (size_t)z*R*C; dlo += (size_t)z*R*C;
    __shared__ float t[32][33];
    int r0 = blockIdx.y*32, c0 = blockIdx.x*32;
    int tx = threadIdx.x, ty = threadIdx.y;
    #pragma unroll
    for (int i = ty; i < 32; i += 8)
        t[i][tx] = src[(size_t)(r0+i)*C + c0 + tx];
    __syncthreads();
    #pragma unroll
    for (int i = ty; i < 32; i += 8){
        float v = t[tx][i];
        __nv_bfloat16 hi, lo; split_bf16(v, hi, lo);
        dhi[(size_t)(c0+i)*R + r0 + tx] = hi;
        dlo[(size_t)(c0+i)*R + r0 + tx] = lo;
    }
}

__global__ void tsplit_ht(){   // g_hf [b][n][d] -> g_th/g_tl [b][d][n]
    int z = blockIdx.z;
    const float* src = g_hf + (size_t)z*262144;
    __nv_bfloat16* dhi = g_th + (size_t)z*262144;
    __nv_bfloat16* dlo = g_tl + (size_t)z*262144;
    __shared__ float t[32][33];
    int r0 = blockIdx.y*32, c0 = blockIdx.x*32;   // r=n (256), c=d (1024)
    int tx = threadIdx.x, ty = threadIdx.y;
    #pragma unroll
    for (int i = ty; i < 32; i += 8)
        t[i][tx] = src[(size_t)(r0+i)*1024 + c0 + tx];
    __syncthreads();
    #pragma unroll
    for (int i = ty; i < 32; i += 8){
        float v = t[tx][i];
        __nv_bfloat16 hi, lo; split_bf16(v, hi, lo);
        dhi[(size_t)(c0+i)*256 + r0 + tx] = hi;
        dlo[(size_t)(c0+i)*256 + r0 + tx] = lo;
    }
}

// ---------------- adaLN SIMT GEMM (small) -------------------------------------
__global__ void zero_mod_kernel(){
    int i = blockIdx.x*1024 + threadIdx.x;
    g_mod[i] = 0.f;
}

__global__ __launch_bounds__(256) void gemm_mod(const float* __restrict__ Aext,
                                                const float* __restrict__ W){
    const int tid = threadIdx.x;
    const int n0 = blockIdx.x * 128;
    const int kbeg = blockIdx.z * 128, kend = kbeg + 128;
    __shared__ __align__(16) float As[8][132];
    __shared__ __align__(16) float Bs[8][132];
    float acc[8][8];
    #pragma unroll
    for (int i=0;i<8;i++) for (int j=0;j<8;j++) acc[i][j] = 0.f;
    const int tx = tid & 15, ty = tid >> 4;
    for (int k0 = kbeg; k0 < kend; k0 += 8){
        #pragma unroll
        for (int j=0;j<4;j++){
            int i = tid + j*256;
            int m = i >> 3, kk = i & 7;
            As[kk][m] = (m < B_) ? silu_f(Aext[m*1024 + k0 + kk]) : 0.f;
        }
        #pragma unroll
        for (int j=0;j<4;j++){
            int i = tid + j*256;
            int kk = i >> 7, n = i & 127;
            Bs[kk][n] = W[(size_t)(k0+kk)*6144 + n0 + n];
        }
        __syncthreads();
        #pragma unroll
        for (int kk=0; kk<8; kk++){
            float a[8], b[8];
            #pragma unroll
            for (int i=0;i<8;i++) a[i] = As[kk][ty*8+i];
            #pragma unroll
            for (int j=0;j<8;j++) b[j] = Bs[kk][tx*8+j];
            #pragma unroll
            for (int i=0;i<8;i++)
                #pragma unroll
                for (int j=0;j<8;j++) acc[i][j] = fmaf(a[i], b[j], acc[i][j]);
        }
        __syncthreads();
    }
    #pragma unroll
    for (int i=0;i<8;i++){
        int m = ty*8 + i;
        if (m >= B_) continue;
        #pragma unroll
        for (int j=0;j<8;j++){
            int n = n0 + tx*8 + j;
            atomicAdd(&g_mod[m*6144 + n], acc[i][j]);
        }
    }
}

// ---------------- elementwise / routing kernels ------------------------------
__global__ void ew1_kernel(const float* __restrict__ x, const float* __restrict__ b_ada){
    int r = blockIdx.x, b = r >> 8, tid = threadIdx.x;
    const float* xr = x + (size_t)r*D_;
    float v[4];
    #pragma unroll
    for (int k=0;k<4;k++) v[k] = xr[tid*4+k];
    float s = v[0]+v[1]+v[2]+v[3];
    float q = v[0]*v[0]+v[1]*v[1]+v[2]*v[2]+v[3]*v[3];
    __shared__ float rs[256], rq[256];
    rs[tid]=s; rq[tid]=q; __syncthreads();
    for (int st=128; st>0; st>>=1){
        if (tid<st){ rs[tid]+=rs[tid+st]; rq[tid]+=rq[tid+st]; }
        __syncthreads();
    }
    float mu  = rs[0]*(1.f/1024.f);
    float var = rq[0]*(1.f/1024.f) - mu*mu;
    float rstd = rsqrtf(var + 1e-6f);
    #pragma unroll
    for (int k=0;k<4;k++){
        int d = tid*4+k;
        float sft = g_mod[b*6144 + d]      + b_ada[d];
        float scl = g_mod[b*6144 + D_ + d] + b_ada[D_ + d];
        float h = (v[k]-mu)*rstd*(1.f+scl) + sft;
        size_t o = (size_t)r*D_ + d;
        g_hf[o] = h;
        __nv_bfloat16 hi, lo; split_bf16(h, hi, lo);
        g_ah[o] = hi; g_al[o] = lo;
        g_mix[o] = 0.f;
    }
}

__global__ void rin_kernel(){
    int b = blockIdx.y;
    int d = blockIdx.x*256 + threadIdx.x;
    const float* hb = g_hf + (size_t)b*N_*D_;
    float s = 0.f;
    for (int n=0;n<N_;n++) s += hb[(size_t)n*D_ + d];
    g_rin[b*D_ + d] = s * (1.f/256.f);
}

__global__ void route_kernel(const float* __restrict__ wr){
    int b = blockIdx.x, tid = threadIdx.x;
    float acc[E_] = {0,0,0,0,0,0,0,0};
    for (int d=tid; d<D_; d+=256){
        float v = g_rin[b*D_ + d];
        #pragma unroll
        for (int e=0;e<E_;e++) acc[e] = fmaf(v, wr[d*E_ + e], acc[e]);
    }
    __shared__ float red[256];
    __shared__ float slog[E_];
    for (int e=0;e<E_;e++){
        red[tid] = acc[e];
        __syncthreads();
        for (int st=128; st>0; st>>=1){
            if (tid<st) red[tid] += red[tid+st];
            __syncthreads();
        }
        if (tid==0) slog[e] = red[0];
        __syncthreads();
    }
    if (tid==0){
        float p[E_];
        float mx = slog[0];
        for (int e=1;e<E_;e++) mx = fmaxf(mx, slog[e]);
        float ssum = 0.f;
        for (int e=0;e<E_;e++){ p[e] = expf(slog[e]-mx); ssum += p[e]; }
        for (int e=0;e<E_;e++){ p[e] /= ssum; g_probs[b*E_+e] = p[e]; }
        int i0 = 0;
        for (int e=1;e<E_;e++) if (p[e] > p[i0]) i0 = e;
        int i1 = (i0==0) ? 1 : 0;
        for (int e=0;e<E_;e++) if (e!=i0 && p[e] > p[i1]) i1 = e;
        float t = p[i0] + p[i1];
        for (int e=0;e<E_;e++){ g_combine[b*E_+e] = 0.f; g_slot[b*E_+e] = 255u; }
        g_combine[b*E_+i0] = p[i0]/t;  g_slot[b*E_+i0] = 0u;
        g_combine[b*E_+i1] = p[i1]/t;  g_slot[b*E_+i1] = 1u;
        g_top1[b] = i0;
    }
}

__global__ void aux_kernel(float* __restrict__ outp, int out_size){
    if (threadIdx.x != 0) return;
    float meanp[E_]; int cnt[E_];
    for (int e=0;e<E_;e++){ meanp[e]=0.f; cnt[e]=0; }
    for (int b=0;b<B_;b++){
        for (int e=0;e<E_;e++) meanp[e] += g_probs[b*E_+e];
        cnt[g_top1[b]]++;
    }
    float aux = 0.f;
    for (int e=0;e<E_;e++) aux += (meanp[e]*(1.f/B_)) * ((float)cnt[e]*(1.f/B_));
    aux *= (float)E_;
    if (out_size > BND) outp[BND] = aux;
}

__global__ void ew2_kernel(const float* __restrict__ x, const float* __restrict__ b_ada,
                           float* __restrict__ outp){
    int r = blockIdx.x, b = r >> 8, tid = threadIdx.x;
    float v[4];
    #pragma unroll
    for (int k=0;k<4;k++){
        int d = tid*4+k;
        float g = g_mod[b*6144 + 2*D_ + d] + b_ada[2*D_ + d];
        float x1 = x[(size_t)r*D_ + d] + g * g_mix[(size_t)r*D_ + d];
        outp[(size_t)r*D_ + d] = x1;
        v[k] = x1;
    }
    float s = v[0]+v[1]+v[2]+v[3];
    float q = v[0]*v[0]+v[1]*v[1]+v[2]*v[2]+v[3]*v[3];
    __shared__ float rs[256], rq[256];
    rs[tid]=s; rq[tid]=q; __syncthreads();
    for (int st=128; st>0; st>>=1){
        if (tid<st){ rs[tid]+=rs[tid+st]; rq[tid]+=rq[tid+st]; }
        __syncthreads();
    }
    float mu  = rs[0]*(1.f/1024.f);
    float var = rq[0]*(1.f/1024.f) - mu*mu;
    float rstd = rsqrtf(var + 1e-6f);
    #pragma unroll
    for (int k=0;k<4;k++){
        int d = tid*4+k;
        float sft = g_mod[b*6144 + 3*D_ + d] + b_ada[3*D_ + d];
        float scl = g_mod[b*6144 + 4*D_ + d] + b_ada[4*D_ + d];
        float h2 = (v[k]-mu)*rstd*(1.f+scl) + sft;
        size_t o = (size_t)r*D_ + d;
        __nv_bfloat16 hi, lo; split_bf16(h2, hi, lo);
        g_ah[o] = hi; g_al[o] = lo;
    }
}

// ---------------- launch ------------------------------------------------------
extern "C" void kernel_launch(void* const* d_in, const int* in_sizes, int n_in,
                              void* d_out, int out_size) {
    const float* x        = (const float*)d_in[0];
    const float* c        = (const float*)d_in[1];
    const float* w_ada    = (const float*)d_in[2];
    const float* b_ada    = (const float*)d_in[3];
    const float* w_router = (const float*)d_in[4];
    const float* tm_w1    = (const float*)d_in[5];
    const float* tm_b1    = (const float*)d_in[6];
    const float* tm_w2    = (const float*)d_in[7];
    const float* tm_b2    = (const float*)d_in[8];
    const float* cm_w1    = (const float*)d_in[9];
    const float* cm_b1    = (const float*)d_in[10];
    const float* cm_w2    = (const float*)d_in[11];
    const float* cm_b2    = (const float*)d_in[12];
    const float* mlp_w1   = (const float*)d_in[13];
    const float* mlp_b1   = (const float*)d_in[14];
    const float* mlp_w2   = (const float*)d_in[15];
    const float* mlp_b2   = (const float*)d_in[16];
    float* outp = (float*)d_out;

    static int attr_done = 0;
    if (!attr_done){
        cudaFuncSetAttribute(tgemm<T_TOK1>, cudaFuncAttributeMaxDynamicSharedMemorySize, SMEM_BYTES);
        cudaFuncSetAttribute(tgemm<T_TOK2>, cudaFuncAttributeMaxDynamicSharedMemorySize, SMEM_BYTES);
        cudaFuncSetAttribute(tgemm<T_CH1>,  cudaFuncAttributeMaxDynamicSharedMemorySize, SMEM_BYTES);
        cudaFuncSetAttribute(tgemm<T_CH2>,  cudaFuncAttributeMaxDynamicSharedMemorySize, SMEM_BYTES);
        cudaFuncSetAttribute(tgemm<T_MLP1>, cudaFuncAttributeMaxDynamicSharedMemorySize, SMEM_BYTES);
        cudaFuncSetAttribute(tgemm<T_MLP2>, cudaFuncAttributeMaxDynamicSharedMemorySize, SMEM_BYTES);
        attr_done = 1;
    }

    // adaLN modulation (SIMT, K-split atomic into zeroed g_mod)
    zero_mod_kernel<<<384, 1024>>>();
    gemm_mod<<<dim3(48,1,8), 256>>>(c, w_ada);

    // weight transpose + bf16 split:  W[K,N] fp32 -> Wt_hi/lo [N,K] bf16
    dim3 tb(32,8);
    __nv_bfloat16 *wh, *wl;
    cudaGetSymbolAddress((void**)&wh, g_wh);
    cudaGetSymbolAddress((void**)&wl, g_wl);
    tsplit<<<dim3(1024/32, 256/32, 4), tb>>>(tm_w1,  wh+OFF_TM1,  wl+OFF_TM1,  256, 1024);
    tsplit<<<dim3(256/32, 1024/32, 4), tb>>>(tm_w2,  wh+OFF_TM2,  wl+OFF_TM2,  1024, 256);
    tsplit<<<dim3(4096/32,1024/32, 4), tb>>>(cm_w1,  wh+OFF_CM1,  wl+OFF_CM1,  1024, 4096);
    tsplit<<<dim3(1024/32,4096/32, 4), tb>>>(cm_w2,  wh+OFF_CM2,  wl+OFF_CM2,  4096, 1024);
    tsplit<<<dim3(4096/32,1024/32, 1), tb>>>(mlp_w1, wh+OFF_MLP1, wl+OFF_MLP1, 1024, 4096);
    tsplit<<<dim3(1024/32,4096/32, 1), tb>>>(mlp_w2, wh+OFF_MLP2, wl+OFF_MLP2, 4096, 1024);

    // LN + modulate; split h; zero mix
    ew1_kernel<<<B_*N_, 256>>>(x, b_ada);
    // h^T split for token experts
    tsplit_ht<<<dim3(32, 8, 64), tb>>>();

    // routing
    rin_kernel<<<dim3(4, B_), 256>>>();
    route_kernel<<<B_, 256>>>(w_router);
    aux_kernel<<<1, 32>>>(outp, out_size);

    // routed experts (tensor cores via mma.sync, gated per (sample, expert))
    tgemm<T_TOK1><<<dim3( 8, 8, B_*4), 256, SMEM_BYTES>>>(tm_b1, nullptr, nullptr);
    tgemm<T_CH1> <<<dim3(32, 2, B_*4), 256, SMEM_BYTES>>>(cm_b1, nullptr, nullptr);
    tgemm<T_TOK2><<<dim3( 2, 8, B_*4), 256, SMEM_BYTES>>>(tm_b2, nullptr, nullptr);
    tgemm<T_CH2> <<<dim3( 8, 2, B_*4), 256, SMEM_BYTES>>>(cm_b2, nullptr, nullptr);

    // residual + second LN/modulate (x1 staged in d_out)
    ew2_kernel<<<B_*N_, 256>>>(x, b_ada, outp);

    // dense MLP (tensor cores), second residual fused into MLP2 epilogue
    tgemm<T_MLP1><<<dim3(32, 128, 1), 256, SMEM_BYTES>>>(mlp_b1, nullptr, nullptr);
    tgemm<T_MLP2><<<dim3( 8, 128, 1), 256, SMEM_BYTES>>>(mlp_b2, b_ada, outp);
}

// round 6
// speedup vs baseline: 2.7529x; 1.0201x over previous
#include <cuda_runtime.h>
#include <cuda_bf16.h>
#include <math.h>
#include <cstdint>

// Problem dims
#define B_   64
#define N_   256
#define D_   1024
#define E_   8
#define BND  (B_*N_*D_)   // 16777216

// ---------------- weight-transpose offsets (elements) ------------------------
#define OFF_TM1  0u
#define OFF_TM2  1048576u
#define OFF_CM1  2097152u
#define OFF_CM2  18874368u
#define OFF_MLP1 35651584u
#define OFF_MLP2 39845888u
#define WT_TOTAL 44040192u

// ---------------- device scratch (allocation-free: __device__ globals) ------
__device__ float g_hf[BND];                        // fp32 h (router + transpose source)
__device__ float g_mix[BND];                       // mixer accumulation
__device__ __nv_bfloat16 g_ah[BND], g_al[BND];     // h / h2 split  [b][n][d]
__device__ __nv_bfloat16 g_th[BND], g_tl[BND];     // h^T split     [b][d][n]
__device__ __nv_bfloat16 g_eh[134217728], g_el[134217728];  // hidden (expert slots / MLP)
__device__ __nv_bfloat16 g_wh[WT_TOTAL], g_wl[WT_TOTAL];    // transposed split weights [N][K]
__device__ float g_mod[B_*6144];
__device__ float g_rin[B_*D_];
__device__ float g_probs[B_*E_];
__device__ float g_combine[B_*E_];
__device__ int   g_top1[B_];
__device__ unsigned char g_slot[B_*E_];

// ---------------- math helpers ----------------------------------------------
__device__ __forceinline__ float gelu_f(float x){
    const float c0 = 0.7978845608028654f;
    float x3 = x*x*x;
    float t = tanhf(c0*(x + 0.044715f*x3));
    return 0.5f*x*(1.0f+t);
}
__device__ __forceinline__ float silu_f(float x){ return x / (1.0f + __expf(-x)); }

__device__ __forceinline__ void split_bf16(float v, __nv_bfloat16& hi, __nv_bfloat16& lo){
    hi = __float2bfloat16(v);
    lo = __float2bfloat16(v - __bfloat162float(hi));
}

// ---------------- PTX helpers ------------------------------------------------
__device__ __forceinline__ uint32_t smem_u32(const void* p){
    uint32_t a;
    asm("{ .reg .u64 t; cvta.to.shared.u64 t, %1; cvt.u32.u64 %0, t; }" : "=r"(a) : "l"(p));
    return a;
}
__device__ __forceinline__ void cpa16(uint32_t dst, const void* src){
    asm volatile("cp.async.cg.shared.global [%0], [%1], 16;" :: "r"(dst), "l"(src));
}
#define CP_COMMIT()  asm volatile("cp.async.commit_group;" ::: "memory")
#define CP_WAIT(n)   asm volatile("cp.async.wait_group %0;" :: "n"(n) : "memory")

// bf16 m16n8k16 tensor-core MMA, fp32 accum (baseline PTX)
#define MMA16816(c, a, b) \
    asm volatile("mma.sync.aligned.m16n8k16.row.col.f32.bf16.bf16.f32 " \
        "{%0,%1,%2,%3}, {%4,%5,%6,%7}, {%8,%9}, {%0,%1,%2,%3};" \
        : "+f"((c)[0]), "+f"((c)[1]), "+f"((c)[2]), "+f"((c)[3]) \
        : "r"((a)[0]), "r"((a)[1]), "r"((a)[2]), "r"((a)[3]), "r"((b)[0]), "r"((b)[1]))

// ldmatrix x4 (baseline PTX, sm_75+)
#define LDSM4(r0,r1,r2,r3,addr) \
    asm volatile("ldmatrix.sync.aligned.m8n8.x4.shared.b16 {%0,%1,%2,%3}, [%4];" \
        : "=r"(r0), "=r"(r1), "=r"(r2), "=r"(r3) : "r"(addr))

// ---------------- tensor GEMM: D = Ah*Bh^T + Ah*Bl^T + Al*Bh^T ---------------
// 128x128 block tile, BK=64, 256 threads (8 warps, each 32m x 64n).
// smem tiles: 128 rows x 64 bf16, row pitch 144B (conflict-free for ldmatrix).
enum { T_TOK1=0, T_TOK2=1, T_CH1=2, T_CH2=3, T_MLP1=4, T_MLP2=5 };

#define TILE_B    18432           // 128 * 144
#define STAGE_B   73728           // 4 tiles
#define SMEM_BYTES 147456         // 2 stages

__device__ __forceinline__ void ld_chunk(uint32_t sb, int s,
    const __nv_bfloat16* Ah, const __nv_bfloat16* Al,
    const __nv_bfloat16* Bh, const __nv_bfloat16* Bl,
    int m0, int n0, int k0, int ldk, int tid)
{
    #pragma unroll
    for (int t=0;t<4;t++){
        int j = tid + t*256;
        int r = j >> 3, c16 = j & 7;
        uint32_t d0 = sb + (uint32_t)s*STAGE_B + r*144 + c16*16;
        size_t ga = (size_t)(m0 + r)*ldk + k0 + c16*8;
        size_t gb = (size_t)(n0 + r)*ldk + k0 + c16*8;
        cpa16(d0,             Ah + ga);
        cpa16(d0 +   TILE_B,  Al + ga);
        cpa16(d0 + 2*TILE_B,  Bh + gb);
        cpa16(d0 + 3*TILE_B,  Bl + gb);
    }
    CP_COMMIT();
}

template<int MODE>
__global__ __launch_bounds__(256) void tgemm(const float* __restrict__ bias,
                                             const float* __restrict__ b_ada,
                                             float* __restrict__ outp)
{
    constexpr int Ktot = (MODE==T_TOK1)?256 : (MODE==T_CH2||MODE==T_MLP2)?4096 : 1024;
    constexpr int NC   = Ktot/64;

    const int tid = threadIdx.x;
    const int wid = tid >> 5, lid = tid & 31;
    const int m0 = blockIdx.y*128, n0 = blockIdx.x*128;
    const int warpM = wid & 3, warpN = wid >> 2;
    const int g = lid >> 2, q = lid & 3;

    const __nv_bfloat16 *Ah, *Al, *Bh, *Bl;
    const float* be = bias;
    float wgt = 0.f; float* mixp = nullptr;
    __nv_bfloat16 *Ch = nullptr, *Cl = nullptr;
    constexpr int ldc = (MODE==T_TOK1)?1024 : (MODE==T_CH1||MODE==T_MLP1)?4096 : 1;

    if constexpr (MODE==T_TOK1||MODE==T_TOK2||MODE==T_CH1||MODE==T_CH2){
        int b = blockIdx.z >> 2, e = blockIdx.z & 3;
        int eg = (MODE==T_CH1||MODE==T_CH2) ? 4+e : e;
        unsigned char sl = g_slot[b*E_ + eg];
        if (sl == 255u) return;
        size_t so = (size_t)(b*2 + sl) * 1048576u;
        if constexpr (MODE==T_TOK1){
            Ah = g_th + (size_t)b*262144; Al = g_tl + (size_t)b*262144;
            Bh = g_wh + OFF_TM1 + (size_t)e*262144; Bl = g_wl + OFF_TM1 + (size_t)e*262144;
            be = bias + e*1024; Ch = g_eh + so; Cl = g_el + so;
        } else if constexpr (MODE==T_TOK2){
            Ah = g_eh + so; Al = g_el + so;
            Bh = g_wh + OFF_TM2 + (size_t)e*262144; Bl = g_wl + OFF_TM2 + (size_t)e*262144;
            be = bias + e*256; mixp = g_mix + (size_t)b*262144; wgt = g_combine[b*E_ + eg];
        } else if constexpr (MODE==T_CH1){
            Ah = g_ah + (size_t)b*262144; Al = g_al + (size_t)b*262144;
            Bh = g_wh + OFF_CM1 + (size_t)e*4194304; Bl = g_wl + OFF_CM1 + (size_t)e*4194304;
            be = bias + e*4096; Ch = g_eh + so; Cl = g_el + so;
        } else {
            Ah = g_eh + so; Al = g_el + so;
            Bh = g_wh + OFF_CM2 + (size_t)e*4194304; Bl = g_wl + OFF_CM2 + (size_t)e*4194304;
            be = bias + e*1024; mixp = g_mix + (size_t)b*262144; wgt = g_combine[b*E_ + eg];
        }
    } else if constexpr (MODE==T_MLP1){
        Ah = g_ah; Al = g_al; Bh = g_wh + OFF_MLP1; Bl = g_wl + OFF_MLP1;
        Ch = g_eh; Cl = g_el;
    } else {
        Ah = g_eh; Al = g_el; Bh = g_wh + OFF_MLP2; Bl = g_wl + OFF_MLP2;
    }

    extern __shared__ char smem[];
    const uint32_t sbase = smem_u32(smem);

    // per-thread ldmatrix base addresses (tile 0, stage 0, kk=0)
    const uint32_t aA = sbase + (uint32_t)(warpM*32 + (lid & 15))*144 + ((lid >> 4)*8)*2;
    const uint32_t aB = sbase + 2*TILE_B
                      + (uint32_t)(warpN*64 + ((lid >> 4)*8) + (lid & 7))*144
                      + (((lid >> 3) & 1)*8)*2;

    float acc[2][8][4];
    #pragma unroll
    for (int i=0;i<2;i++)
        #pragma unroll
        for (int j=0;j<8;j++)
            #pragma unroll
            for (int k=0;k<4;k++) acc[i][j][k] = 0.f;

    ld_chunk(sbase, 0, Ah, Al, Bh, Bl, m0, n0, 0, Ktot, tid);

    for (int c = 0; c < NC; c++){
        int s = c & 1;
        if (c + 1 < NC){
            ld_chunk(sbase, s^1, Ah, Al, Bh, Bl, m0, n0, (c+1)*64, Ktot, tid);
            CP_WAIT(1);
        } else {
            CP_WAIT(0);
        }
        __syncthreads();

        const uint32_t sOff = (uint32_t)s*STAGE_B;

        #pragma unroll
        for (int kk = 0; kk < 64; kk += 16){
            uint32_t afh[2][4], afl[2][4];
            #pragma unroll
            for (int ma=0;ma<2;ma++){
                uint32_t base = aA + sOff + ma*2304 + kk*2;
                LDSM4(afh[ma][0], afh[ma][1], afh[ma][2], afh[ma][3], base);
                LDSM4(afl[ma][0], afl[ma][1], afl[ma][2], afl[ma][3], base + TILE_B);
            }
            uint32_t bfh[8][2], bfl[8][2];
            #pragma unroll
            for (int p=0;p<4;p++){
                uint32_t base = aB + sOff + p*2304 + kk*2;
                LDSM4(bfh[2*p][0], bfh[2*p][1], bfh[2*p+1][0], bfh[2*p+1][1], base);
                LDSM4(bfl[2*p][0], bfl[2*p][1], bfl[2*p+1][0], bfl[2*p+1][1], base + TILE_B);
            }
            #pragma unroll
            for (int ma=0;ma<2;ma++)
                #pragma unroll
                for (int nb=0;nb<8;nb++){
                    MMA16816(acc[ma][nb], afh[ma], bfh[nb]);   // Ah*Bh
                    MMA16816(acc[ma][nb], afh[ma], bfl[nb]);   // Ah*Bl
                    MMA16816(acc[ma][nb], afl[ma], bfh[nb]);   // Al*Bh
                }
        }
        __syncthreads();
    }

    // ---- epilogue ----
    #pragma unroll
    for (int ma=0;ma<2;ma++){
        #pragma unroll
        for (int nb=0;nb<8;nb++){
            int r0 = m0 + warpM*32 + ma*16 + g;
            int nc = n0 + warpN*64 + nb*8 + q*2;
            #pragma unroll
            for (int hv=0;hv<2;hv++){            // hv=0: rows r0, hv=1: rows r0+8
                int m = r0 + hv*8;
                #pragma unroll
                for (int jj=0;jj<2;jj++){
                    int n = nc + jj;
                    float v = acc[ma][nb][hv*2+jj] + be[n];
                    if constexpr (MODE==T_TOK1 || MODE==T_CH1 || MODE==T_MLP1){
                        float gg = gelu_f(v);
                        __nv_bfloat16 hi, lo; split_bf16(gg, hi, lo);
                        Ch[(size_t)m*ldc + n] = hi;
                        Cl[(size_t)m*ldc + n] = lo;
                    } else if constexpr (MODE==T_TOK2){
                        atomicAdd(&mixp[(size_t)n*D_ + m], wgt * v);   // m=d, n=token
                    } else if constexpr (MODE==T_CH2){
                        atomicAdd(&mixp[(size_t)m*D_ + n], wgt * v);
                    } else { // MLP2
                        int bb = m >> 8;
                        float gml = g_mod[bb*6144 + 5120 + n] + b_ada[5120 + n];
                        size_t o = (size_t)m*D_ + n;
                        outp[o] = outp[o] + gml * v;
                    }
                }
            }
        }
    }
}

// ---------------- transpose + bf16-split kernels ------------------------------
__global__ void tsplit(const float* __restrict__ src, __nv_bfloat16* __restrict__ dhi,
                       __nv_bfloat16* __restrict__ dlo, int R, int C){
    int z = blockIdx.z;
    src += (size_t)z*R*C; dhi += (size_t)z*R*C; dlo += (size_t)z*R*C;
    __shared__ float t[32][33];
    int r0 = blockIdx.y*32, c0 = blockIdx.x*32;
    int tx = threadIdx.x, ty = threadIdx.y;
    #pragma unroll
    for (int i = ty; i < 32; i += 8)
        t[i][tx] = src[(size_t)(r0+i)*C + c0 + tx];
    __syncthreads();
    #pragma unroll
    for (int i = ty; i < 32; i += 8){
        float v = t[tx][i];
        __nv_bfloat16 hi, lo; split_bf16(v, hi, lo);
        dhi[(size_t)(c0+i)*R + r0 + tx] = hi;
        dlo[(size_t)(c0+i)*R + r0 + tx] = lo;
    }
}

__global__ void tsplit_ht(){   // g_hf [b][n][d] -> g_th/g_tl [b][d][n]
    int z = blockIdx.z;
    const float* src = g_hf + (size_t)z*262144;
    __nv_bfloat16* dhi = g_th + (size_t)z*262144;
    __nv_bfloat16* dlo = g_tl + (size_t)z*262144;
    __shared__ float t[32][33];
    int r0 = blockIdx.y*32, c0 = blockIdx.x*32;   // r=n (256), c=d (1024)
    int tx = threadIdx.x, ty = threadIdx.y;
    #pragma unroll
    for (int i = ty; i < 32; i += 8)
        t[i][tx] = src[(size_t)(r0+i)*1024 + c0 + tx];
    __syncthreads();
    #pragma unroll
    for (int i = ty; i < 32; i += 8){
        float v = t[tx][i];
        __nv_bfloat16 hi, lo; split_bf16(v, hi, lo);
        dhi[(size_t)(c0+i)*256 + r0 + tx] = hi;
        dlo[(size_t)(c0+i)*256 + r0 + tx] = lo;
    }
}

// ---------------- adaLN SIMT GEMM (small) -------------------------------------
__global__ void zero_mod_kernel(){
    int i = blockIdx.x*1024 + threadIdx.x;
    g_mod[i] = 0.f;
}

__global__ __launch_bounds__(256) void gemm_mod(const float* __restrict__ Aext,
                                                const float* __restrict__ W){
    const int tid = threadIdx.x;
    const int n0 = blockIdx.x * 128;
    const int kbeg = blockIdx.z * 128, kend = kbeg + 128;
    __shared__ __align__(16) float As[8][132];
    __shared__ __align__(16) float Bs[8][132];
    float acc[8][8];
    #pragma unroll
    for (int i=0;i<8;i++) for (int j=0;j<8;j++) acc[i][j] = 0.f;
    const int tx = tid & 15, ty = tid >> 4;
    for (int k0 = kbeg; k0 < kend; k0 += 8){
        #pragma unroll
        for (int j=0;j<4;j++){
            int i = tid + j*256;
            int m = i >> 3, kk = i & 7;
            As[kk][m] = (m < B_) ? silu_f(Aext[m*1024 + k0 + kk]) : 0.f;
        }
        #pragma unroll
        for (int j=0;j<4;j++){
            int i = tid + j*256;
            int kk = i >> 7, n = i & 127;
            Bs[kk][n] = W[(size_t)(k0+kk)*6144 + n0 + n];
        }
        __syncthreads();
        #pragma unroll
        for (int kk=0; kk<8; kk++){
            float a[8], b[8];
            #pragma unroll
            for (int i=0;i<8;i++) a[i] = As[kk][ty*8+i];
            #pragma unroll
            for (int j=0;j<8;j++) b[j] = Bs[kk][tx*8+j];
            #pragma unroll
            for (int i=0;i<8;i++)
                #pragma unroll
                for (int j=0;j<8;j++) acc[i][j] = fmaf(a[i], b[j], acc[i][j]);
        }
        __syncthreads();
    }
    #pragma unroll
    for (int i=0;i<8;i++){
        int m = ty*8 + i;
        if (m >= B_) continue;
        #pragma unroll
        for (int j=0;j<8;j++){
            int n = n0 + tx*8 + j;
            atomicAdd(&g_mod[m*6144 + n], acc[i][j]);
        }
    }
}

// ---------------- elementwise / routing kernels ------------------------------
__global__ void ew1_kernel(const float* __restrict__ x, const float* __restrict__ b_ada){
    int r = blockIdx.x, b = r >> 8, tid = threadIdx.x;
    const float* xr = x + (size_t)r*D_;
    float v[4];
    #pragma unroll
    for (int k=0;k<4;k++) v[k] = xr[tid*4+k];
    float s = v[0]+v[1]+v[2]+v[3];
    float q = v[0]*v[0]+v[1]*v[1]+v[2]*v[2]+v[3]*v[3];
    __shared__ float rs[256], rq[256];
    rs[tid]=s; rq[tid]=q; __syncthreads();
    for (int st=128; st>0; st>>=1){
        if (tid<st){ rs[tid]+=rs[tid+st]; rq[tid]+=rq[tid+st]; }
        __syncthreads();
    }
    float mu  = rs[0]*(1.f/1024.f);
    float var = rq[0]*(1.f/1024.f) - mu*mu;
    float rstd = rsqrtf(var + 1e-6f);
    #pragma unroll
    for (int k=0;k<4;k++){
        int d = tid*4+k;
        float sft = g_mod[b*6144 + d]      + b_ada[d];
        float scl = g_mod[b*6144 + D_ + d] + b_ada[D_ + d];
        float h = (v[k]-mu)*rstd*(1.f+scl) + sft;
        size_t o = (size_t)r*D_ + d;
        g_hf[o] = h;
        __nv_bfloat16 hi, lo; split_bf16(h, hi, lo);
        g_ah[o] = hi; g_al[o] = lo;
        g_mix[o] = 0.f;
    }
}

__global__ void rin_kernel(){
    int b = blockIdx.y;
    int d = blockIdx.x*256 + threadIdx.x;
    const float* hb = g_hf + (size_t)b*N_*D_;
    float s = 0.f;
    for (int n=0;n<N_;n++) s += hb[(size_t)n*D_ + d];
    g_rin[b*D_ + d] = s * (1.f/256.f);
}

__global__ void route_kernel(const float* __restrict__ wr){
    int b = blockIdx.x, tid = threadIdx.x;
    float acc[E_] = {0,0,0,0,0,0,0,0};
    for (int d=tid; d<D_; d+=256){
        float v = g_rin[b*D_ + d];
        #pragma unroll
        for (int e=0;e<E_;e++) acc[e] = fmaf(v, wr[d*E_ + e], acc[e]);
    }
    __shared__ float red[256];
    __shared__ float slog[E_];
    for (int e=0;e<E_;e++){
        red[tid] = acc[e];
        __syncthreads();
        for (int st=128; st>0; st>>=1){
            if (tid<st) red[tid] += red[tid+st];
            __syncthreads();
        }
        if (tid==0) slog[e] = red[0];
        __syncthreads();
    }
    if (tid==0){
        float p[E_];
        float mx = slog[0];
        for (int e=1;e<E_;e++) mx = fmaxf(mx, slog[e]);
        float ssum = 0.f;
        for (int e=0;e<E_;e++){ p[e] = expf(slog[e]-mx); ssum += p[e]; }
        for (int e=0;e<E_;e++){ p[e] /= ssum; g_probs[b*E_+e] = p[e]; }
        int i0 = 0;
        for (int e=1;e<E_;e++) if (p[e] > p[i0]) i0 = e;
        int i1 = (i0==0) ? 1 : 0;
        for (int e=0;e<E_;e++) if (e!=i0 && p[e] > p[i1]) i1 = e;
        float t = p[i0] + p[i1];
        for (int e=0;e<E_;e++){ g_combine[b*E_+e] = 0.f; g_slot[b*E_+e] = 255u; }
        g_combine[b*E_+i0] = p[i0]/t;  g_slot[b*E_+i0] = 0u;
        g_combine[b*E_+i1] = p[i1]/t;  g_slot[b*E_+i1] = 1u;
        g_top1[b] = i0;
    }
}

__global__ void aux_kernel(float* __restrict__ outp, int out_size){
    if (threadIdx.x != 0) return;
    float meanp[E_]; int cnt[E_];
    for (int e=0;e<E_;e++){ meanp[e]=0.f; cnt[e]=0; }
    for (int b=0;b<B_;b++){
        for (int e=0;e<E_;e++) meanp[e] += g_probs[b*E_+e];
        cnt[g_top1[b]]++;
    }
    float aux = 0.f;
    for (int e=0;e<E_;e++) aux += (meanp[e]*(1.f/B_)) * ((float)cnt[e]*(1.f/B_));
    aux *= (float)E_;
    if (out_size > BND) outp[BND] = aux;
}

__global__ void ew2_kernel(const float* __restrict__ x, const float* __restrict__ b_ada,
                           float* __restrict__ outp){
    int r = blockIdx.x, b = r >> 8, tid = threadIdx.x;
    float v[4];
    #pragma unroll
    for (int k=0;k<4;k++){
        int d = tid*4+k;
        float g = g_mod[b*6144 + 2*D_ + d] + b_ada[2*D_ + d];
        float x1 = x[(size_t)r*D_ + d] + g * g_mix[(size_t)r*D_ + d];
        outp[(size_t)r*D_ + d] = x1;
        v[k] = x1;
    }
    float s = v[0]+v[1]+v[2]+v[3];
    float q = v[0]*v[0]+v[1]*v[1]+v[2]*v[2]+v[3]*v[3];
    __shared__ float rs[256], rq[256];
    rs[tid]=s; rq[tid]=q; __syncthreads();
    for (int st=128; st>0; st>>=1){
        if (tid<st){ rs[tid]+=rs[tid+st]; rq[tid]+=rq[tid+st]; }
        __syncthreads();
    }
    float mu  = rs[0]*(1.f/1024.f);
    float var = rq[0]*(1.f/1024.f) - mu*mu;
    float rstd = rsqrtf(var + 1e-6f);
    #pragma unroll
    for (int k=0;k<4;k++){
        int d = tid*4+k;
        float sft = g_mod[b*6144 + 3*D_ + d] + b_ada[3*D_ + d];
        float scl = g_mod[b*6144 + 4*D_ + d] + b_ada[4*D_ + d];
        float h2 = (v[k]-mu)*rstd*(1.f+scl) + sft;
        size_t o = (size_t)r*D_ + d;
        __nv_bfloat16 hi, lo; split_bf16(h2, hi, lo);
        g_ah[o] = hi; g_al[o] = lo;
    }
}

// ---------------- launch ------------------------------------------------------
extern "C" void kernel_launch(void* const* d_in, const int* in_sizes, int n_in,
                              void* d_out, int out_size) {
    const float* x        = (const float*)d_in[0];
    const float* c        = (const float*)d_in[1];
    const float* w_ada    = (const float*)d_in[2];
    const float* b_ada    = (const float*)d_in[3];
    const float* w_router = (const float*)d_in[4];
    const float* tm_w1    = (const float*)d_in[5];
    const float* tm_b1    = (const float*)d_in[6];
    const float* tm_w2    = (const float*)d_in[7];
    const float* tm_b2    = (const float*)d_in[8];
    const float* cm_w1    = (const float*)d_in[9];
    const float* cm_b1    = (const float*)d_in[10];
    const float* cm_w2    = (const float*)d_in[11];
    const float* cm_b2    = (const float*)d_in[12];
    const float* mlp_w1   = (const float*)d_in[13];
    const float* mlp_b1   = (const float*)d_in[14];
    const float* mlp_w2   = (const float*)d_in[15];
    const float* mlp_b2   = (const float*)d_in[16];
    float* outp = (float*)d_out;

    static int attr_done = 0;
    if (!attr_done){
        cudaFuncSetAttribute(tgemm<T_TOK1>, cudaFuncAttributeMaxDynamicSharedMemorySize, SMEM_BYTES);
        cudaFuncSetAttribute(tgemm<T_TOK2>, cudaFuncAttributeMaxDynamicSharedMemorySize, SMEM_BYTES);
        cudaFuncSetAttribute(tgemm<T_CH1>,  cudaFuncAttributeMaxDynamicSharedMemorySize, SMEM_BYTES);
        cudaFuncSetAttribute(tgemm<T_CH2>,  cudaFuncAttributeMaxDynamicSharedMemorySize, SMEM_BYTES);
        cudaFuncSetAttribute(tgemm<T_MLP1>, cudaFuncAttributeMaxDynamicSharedMemorySize, SMEM_BYTES);
        cudaFuncSetAttribute(tgemm<T_MLP2>, cudaFuncAttributeMaxDynamicSharedMemorySize, SMEM_BYTES);
        attr_done = 1;
    }

    // adaLN modulation (SIMT, K-split atomic into zeroed g_mod)
    zero_mod_kernel<<<384, 1024>>>();
    gemm_mod<<<dim3(48,1,8), 256>>>(c, w_ada);

    // weight transpose + bf16 split:  W[K,N] fp32 -> Wt_hi/lo [N,K] bf16
    dim3 tb(32,8);
    __nv_bfloat16 *wh, *wl;
    cudaGetSymbolAddress((void**)&wh, g_wh);
    cudaGetSymbolAddress((void**)&wl, g_wl);
    tsplit<<<dim3(1024/32, 256/32, 4), tb>>>(tm_w1,  wh+OFF_TM1,  wl+OFF_TM1,  256, 1024);
    tsplit<<<dim3(256/32, 1024/32, 4), tb>>>(tm_w2,  wh+OFF_TM2,  wl+OFF_TM2,  1024, 256);
    tsplit<<<dim3(4096/32,1024/32, 4), tb>>>(cm_w1,  wh+OFF_CM1,  wl+OFF_CM1,  1024, 4096);
    tsplit<<<dim3(1024/32,4096/32, 4), tb>>>(cm_w2,  wh+OFF_CM2,  wl+OFF_CM2,  4096, 1024);
    tsplit<<<dim3(4096/32,1024/32, 1), tb>>>(mlp_w1, wh+OFF_MLP1, wl+OFF_MLP1, 1024, 4096);
    tsplit<<<dim3(1024/32,4096/32, 1), tb>>>(mlp_w2, wh+OFF_MLP2, wl+OFF_MLP2, 4096, 1024);

    // LN + modulate; split h; zero mix
    ew1_kernel<<<B_*N_, 256>>>(x, b_ada);
    // h^T split for token experts
    tsplit_ht<<<dim3(32, 8, 64), tb>>>();

    // routing
    rin_kernel<<<dim3(4, B_), 256>>>();
    route_kernel<<<B_, 256>>>(w_router);
    aux_kernel<<<1, 32>>>(outp, out_size);

    // routed experts (tensor cores via mma.sync + ldmatrix, gated per (sample, expert))
    tgemm<T_TOK1><<<dim3( 8, 8, B_*4), 256, SMEM_BYTES>>>(tm_b1, nullptr, nullptr);
    tgemm<T_CH1> <<<dim3(32, 2, B_*4), 256, SMEM_BYTES>>>(cm_b1, nullptr, nullptr);
    tgemm<T_TOK2><<<dim3( 2, 8, B_*4), 256, SMEM_BYTES>>>(tm_b2, nullptr, nullptr);
    tgemm<T_CH2> <<<dim3( 8, 2, B_*4), 256, SMEM_BYTES>>>(cm_b2, nullptr, nullptr);

    // residual + second LN/modulate (x1 staged in d_out)
    ew2_kernel<<<B_*N_, 256>>>(x, b_ada, outp);

    // dense MLP (tensor cores), second residual fused into MLP2 epilogue
    tgemm<T_MLP1><<<dim3(32, 128, 1), 256, SMEM_BYTES>>>(mlp_b1, nullptr, nullptr);
    tgemm<T_MLP2><<<dim3( 8, 128, 1), 256, SMEM_BYTES>>>(mlp_b2, b_ada, outp);
}

// round 7
// speedup vs baseline: 7.0607x; 2.5648x over previous
#include <cuda_runtime.h>
#include <cuda_fp16.h>
#include <math.h>
#include <cstdint>

// Problem dims
#define B_   64
#define N_   256
#define D_   1024
#define E_   8
#define BND  (B_*N_*D_)   // 16777216

// ---------------- weight-transpose offsets (elements) ------------------------
#define OFF_TM1  0u
#define OFF_TM2  1048576u
#define OFF_CM1  2097152u
#define OFF_CM2  18874368u
#define OFF_MLP1 35651584u
#define OFF_MLP2 39845888u
#define WT_TOTAL 44040192u

// ---------------- device scratch (allocation-free: __device__ globals) ------
__device__ float g_hf[BND];                 // fp32 h (router + transpose source)
__device__ float g_mix[BND];                // mixer accumulation
__device__ __half g_a[BND];                 // h / h2 (fp16)  [b][n][d]
__device__ __half g_t[BND];                 // h^T (fp16)     [b][d][n]
__device__ __half g_e[134217728];           // hidden (expert slots / MLP)
__device__ __half g_w[WT_TOTAL];            // transposed fp16 weights [N][K]
__device__ float g_mod[B_*6144];
__device__ float g_rin[B_*D_];
__device__ float g_probs[B_*E_];
__device__ float g_combine[B_*E_];
__device__ int   g_top1[B_];
__device__ unsigned char g_slot[B_*E_];

// ---------------- math helpers ----------------------------------------------
__device__ __forceinline__ float gelu_f(float x){
    const float c0 = 0.7978845608028654f;
    float x3 = x*x*x;
    float t = tanhf(c0*(x + 0.044715f*x3));
    return 0.5f*x*(1.0f+t);
}
__device__ __forceinline__ float silu_f(float x){ return x / (1.0f + __expf(-x)); }

// ---------------- PTX helpers ------------------------------------------------
__device__ __forceinline__ uint32_t smem_u32(const void* p){
    uint32_t a;
    asm("{ .reg .u64 t; cvta.to.shared.u64 t, %1; cvt.u32.u64 %0, t; }" : "=r"(a) : "l"(p));
    return a;
}
__device__ __forceinline__ void cpa16(uint32_t dst, const void* src){
    asm volatile("cp.async.cg.shared.global [%0], [%1], 16;" :: "r"(dst), "l"(src));
}
#define CP_COMMIT()  asm volatile("cp.async.commit_group;" ::: "memory")
#define CP_WAIT(n)   asm volatile("cp.async.wait_group %0;" :: "n"(n) : "memory")

// fp16 m16n8k16 tensor-core MMA, fp32 accum (baseline PTX)
#define MMA16816(c, a, b) \
    asm volatile("mma.sync.aligned.m16n8k16.row.col.f32.f16.f16.f32 " \
        "{%0,%1,%2,%3}, {%4,%5,%6,%7}, {%8,%9}, {%0,%1,%2,%3};" \
        : "+f"((c)[0]), "+f"((c)[1]), "+f"((c)[2]), "+f"((c)[3]) \
        : "r"((a)[0]), "r"((a)[1]), "r"((a)[2]), "r"((a)[3]), "r"((b)[0]), "r"((b)[1]))

// ldmatrix x4 (baseline PTX, sm_75+)
#define LDSM4(r0,r1,r2,r3,addr) \
    asm volatile("ldmatrix.sync.aligned.m8n8.x4.shared.b16 {%0,%1,%2,%3}, [%4];" \
        : "=r"(r0), "=r"(r1), "=r"(r2), "=r"(r3) : "r"(addr))

// ---------------- tensor GEMM (fp16 single pass) ------------------------------
// 128x128 block tile, BK=64, 256 threads (8 warps, each 32m x 64n), 2 CTAs/SM.
// smem tiles: 128 rows x 64 fp16, row pitch 144B (conflict-free for ldmatrix).
enum { T_TOK1=0, T_TOK2=1, T_CH1=2, T_CH2=3, T_MLP1=4, T_MLP2=5 };

#define TILE_B    18432           // 128 * 144
#define STAGE_B   36864           // 2 tiles (A, B)
#define SMEM_BYTES 73728          // 2 stages

__device__ __forceinline__ void ld_chunk(uint32_t sb, int s,
    const __half* A, const __half* Bv,
    int m0, int n0, int k0, int ldk, int tid)
{
    #pragma unroll
    for (int t=0;t<4;t++){
        int j = tid + t*256;
        int r = j >> 3, c16 = j & 7;
        uint32_t d0 = sb + (uint32_t)s*STAGE_B + r*144 + c16*16;
        cpa16(d0,          A  + (size_t)(m0 + r)*ldk + k0 + c16*8);
        cpa16(d0 + TILE_B, Bv + (size_t)(n0 + r)*ldk + k0 + c16*8);
    }
    CP_COMMIT();
}

template<int MODE>
__global__ __launch_bounds__(256,2) void tgemm(const float* __restrict__ bias,
                                               const float* __restrict__ b_ada,
                                               float* __restrict__ outp)
{
    constexpr int Ktot = (MODE==T_TOK1)?256 : (MODE==T_CH2||MODE==T_MLP2)?4096 : 1024;
    constexpr int NC   = Ktot/64;

    const int tid = threadIdx.x;
    const int wid = tid >> 5, lid = tid & 31;
    const int m0 = blockIdx.y*128, n0 = blockIdx.x*128;
    const int warpM = wid & 3, warpN = wid >> 2;
    const int g = lid >> 2, q = lid & 3;

    const __half *A, *Bv;
    const float* be = bias;
    float wgt = 0.f; float* mixp = nullptr;
    __half* Cp = nullptr;
    constexpr int ldc = (MODE==T_TOK1)?1024 : (MODE==T_CH1||MODE==T_MLP1)?4096 : 1;

    if constexpr (MODE==T_TOK1||MODE==T_TOK2||MODE==T_CH1||MODE==T_CH2){
        int b = blockIdx.z >> 2, e = blockIdx.z & 3;
        int eg = (MODE==T_CH1||MODE==T_CH2) ? 4+e : e;
        unsigned char sl = g_slot[b*E_ + eg];
        if (sl == 255u) return;
        size_t so = (size_t)(b*2 + sl) * 1048576u;
        if constexpr (MODE==T_TOK1){
            A  = g_t + (size_t)b*262144;
            Bv = g_w + OFF_TM1 + (size_t)e*262144;
            be = bias + e*1024; Cp = g_e + so;
        } else if constexpr (MODE==T_TOK2){
            A  = g_e + so;
            Bv = g_w + OFF_TM2 + (size_t)e*262144;
            be = bias + e*256; mixp = g_mix + (size_t)b*262144; wgt = g_combine[b*E_ + eg];
        } else if constexpr (MODE==T_CH1){
            A  = g_a + (size_t)b*262144;
            Bv = g_w + OFF_CM1 + (size_t)e*4194304;
            be = bias + e*4096; Cp = g_e + so;
        } else {
            A  = g_e + so;
            Bv = g_w + OFF_CM2 + (size_t)e*4194304;
            be = bias + e*1024; mixp = g_mix + (size_t)b*262144; wgt = g_combine[b*E_ + eg];
        }
    } else if constexpr (MODE==T_MLP1){
        A = g_a; Bv = g_w + OFF_MLP1; Cp = g_e;
    } else {
        A = g_e; Bv = g_w + OFF_MLP2;
    }

    extern __shared__ char smem[];
    const uint32_t sbase = smem_u32(smem);

    // per-thread ldmatrix base addresses (stage 0, kk=0)
    const uint32_t aA = sbase + (uint32_t)(warpM*32 + (lid & 15))*144 + ((lid >> 4)*8)*2;
    const uint32_t aB = sbase + TILE_B
                      + (uint32_t)(warpN*64 + ((lid >> 4)*8) + (lid & 7))*144
                      + (((lid >> 3) & 1)*8)*2;

    float acc[2][8][4];
    #pragma unroll
    for (int i=0;i<2;i++)
        #pragma unroll
        for (int j=0;j<8;j++)
            #pragma unroll
            for (int k=0;k<4;k++) acc[i][j][k] = 0.f;

    ld_chunk(sbase, 0, A, Bv, m0, n0, 0, Ktot, tid);

    for (int c = 0; c < NC; c++){
        int s = c & 1;
        if (c + 1 < NC){
            ld_chunk(sbase, s^1, A, Bv, m0, n0, (c+1)*64, Ktot, tid);
            CP_WAIT(1);
        } else {
            CP_WAIT(0);
        }
        __syncthreads();

        const uint32_t sOff = (uint32_t)s*STAGE_B;

        #pragma unroll
        for (int kk = 0; kk < 64; kk += 16){
            uint32_t af[2][4];
            #pragma unroll
            for (int ma=0;ma<2;ma++){
                uint32_t base = aA + sOff + ma*2304 + kk*2;
                LDSM4(af[ma][0], af[ma][1], af[ma][2], af[ma][3], base);
            }
            uint32_t bf[8][2];
            #pragma unroll
            for (int p=0;p<4;p++){
                uint32_t base = aB + sOff + p*2304 + kk*2;
                LDSM4(bf[2*p][0], bf[2*p][1], bf[2*p+1][0], bf[2*p+1][1], base);
            }
            #pragma unroll
            for (int ma=0;ma<2;ma++)
                #pragma unroll
                for (int nb=0;nb<8;nb++)
                    MMA16816(acc[ma][nb], af[ma], bf[nb]);
        }
        __syncthreads();
    }

    // ---- epilogue ----
    #pragma unroll
    for (int ma=0;ma<2;ma++){
        #pragma unroll
        for (int nb=0;nb<8;nb++){
            int r0 = m0 + warpM*32 + ma*16 + g;
            int nc = n0 + warpN*64 + nb*8 + q*2;
            #pragma unroll
            for (int hv=0;hv<2;hv++){            // hv=0: rows r0, hv=1: rows r0+8
                int m = r0 + hv*8;
                #pragma unroll
                for (int jj=0;jj<2;jj++){
                    int n = nc + jj;
                    float v = acc[ma][nb][hv*2+jj] + be[n];
                    if constexpr (MODE==T_TOK1 || MODE==T_CH1 || MODE==T_MLP1){
                        Cp[(size_t)m*ldc + n] = __float2half(gelu_f(v));
                    } else if constexpr (MODE==T_TOK2){
                        atomicAdd(&mixp[(size_t)n*D_ + m], wgt * v);   // m=d, n=token
                    } else if constexpr (MODE==T_CH2){
                        atomicAdd(&mixp[(size_t)m*D_ + n], wgt * v);
                    } else { // MLP2
                        int bb = m >> 8;
                        float gml = g_mod[bb*6144 + 5120 + n] + b_ada[5120 + n];
                        size_t o = (size_t)m*D_ + n;
                        outp[o] = outp[o] + gml * v;
                    }
                }
            }
        }
    }
}

// ---------------- transpose + fp16 convert kernels ----------------------------
__global__ void tsplit(const float* __restrict__ src, __half* __restrict__ dst,
                       int R, int C){
    int z = blockIdx.z;
    src += (size_t)z*R*C; dst += (size_t)z*R*C;
    __shared__ float t[32][33];
    int r0 = blockIdx.y*32, c0 = blockIdx.x*32;
    int tx = threadIdx.x, ty = threadIdx.y;
    #pragma unroll
    for (int i = ty; i < 32; i += 8)
        t[i][tx] = src[(size_t)(r0+i)*C + c0 + tx];
    __syncthreads();
    #pragma unroll
    for (int i = ty; i < 32; i += 8)
        dst[(size_t)(c0+i)*R + r0 + tx] = __float2half(t[tx][i]);
}

__global__ void tsplit_ht(){   // g_hf [b][n][d] -> g_t [b][d][n]
    int z = blockIdx.z;
    const float* src = g_hf + (size_t)z*262144;
    __half* dst = g_t + (size_t)z*262144;
    __shared__ float t[32][33];
    int r0 = blockIdx.y*32, c0 = blockIdx.x*32;   // r=n (256), c=d (1024)
    int tx = threadIdx.x, ty = threadIdx.y;
    #pragma unroll
    for (int i = ty; i < 32; i += 8)
        t[i][tx] = src[(size_t)(r0+i)*1024 + c0 + tx];
    __syncthreads();
    #pragma unroll
    for (int i = ty; i < 32; i += 8)
        dst[(size_t)(c0+i)*256 + r0 + tx] = __float2half(t[tx][i]);
}

// ---------------- adaLN SIMT GEMM (small) -------------------------------------
__global__ void zero_mod_kernel(){
    int i = blockIdx.x*1024 + threadIdx.x;
    g_mod[i] = 0.f;
}

__global__ __launch_bounds__(256) void gemm_mod(const float* __restrict__ Aext,
                                                const float* __restrict__ W){
    const int tid = threadIdx.x;
    const int n0 = blockIdx.x * 128;
    const int kbeg = blockIdx.z * 128, kend = kbeg + 128;
    __shared__ __align__(16) float As[8][132];
    __shared__ __align__(16) float Bs[8][132];
    float acc[8][8];
    #pragma unroll
    for (int i=0;i<8;i++) for (int j=0;j<8;j++) acc[i][j] = 0.f;
    const int tx = tid & 15, ty = tid >> 4;
    for (int k0 = kbeg; k0 < kend; k0 += 8){
        #pragma unroll
        for (int j=0;j<4;j++){
            int i = tid + j*256;
            int m = i >> 3, kk = i & 7;
            As[kk][m] = (m < B_) ? silu_f(Aext[m*1024 + k0 + kk]) : 0.f;
        }
        #pragma unroll
        for (int j=0;j<4;j++){
            int i = tid + j*256;
            int kk = i >> 7, n = i & 127;
            Bs[kk][n] = W[(size_t)(k0+kk)*6144 + n0 + n];
        }
        __syncthreads();
        #pragma unroll
        for (int kk=0; kk<8; kk++){
            float a[8], b[8];
            #pragma unroll
            for (int i=0;i<8;i++) a[i] = As[kk][ty*8+i];
            #pragma unroll
            for (int j=0;j<8;j++) b[j] = Bs[kk][tx*8+j];
            #pragma unroll
            for (int i=0;i<8;i++)
                #pragma unroll
                for (int j=0;j<8;j++) acc[i][j] = fmaf(a[i], b[j], acc[i][j]);
        }
        __syncthreads();
    }
    #pragma unroll
    for (int i=0;i<8;i++){
        int m = ty*8 + i;
        if (m >= B_) continue;
        #pragma unroll
        for (int j=0;j<8;j++){
            int n = n0 + tx*8 + j;
            atomicAdd(&g_mod[m*6144 + n], acc[i][j]);
        }
    }
}

// ---------------- elementwise / routing kernels ------------------------------
__global__ void ew1_kernel(const float* __restrict__ x, const float* __restrict__ b_ada){
    int r = blockIdx.x, b = r >> 8, tid = threadIdx.x;
    const float* xr = x + (size_t)r*D_;
    float v[4];
    #pragma unroll
    for (int k=0;k<4;k++) v[k] = xr[tid*4+k];
    float s = v[0]+v[1]+v[2]+v[3];
    float q = v[0]*v[0]+v[1]*v[1]+v[2]*v[2]+v[3]*v[3];
    __shared__ float rs[256], rq[256];
    rs[tid]=s; rq[tid]=q; __syncthreads();
    for (int st=128; st>0; st>>=1){
        if (tid<st){ rs[tid]+=rs[tid+st]; rq[tid]+=rq[tid+st]; }
        __syncthreads();
    }
    float mu  = rs[0]*(1.f/1024.f);
    float var = rq[0]*(1.f/1024.f) - mu*mu;
    float rstd = rsqrtf(var + 1e-6f);
    #pragma unroll
    for (int k=0;k<4;k++){
        int d = tid*4+k;
        float sft = g_mod[b*6144 + d]      + b_ada[d];
        float scl = g_mod[b*6144 + D_ + d] + b_ada[D_ + d];
        float h = (v[k]-mu)*rstd*(1.f+scl) + sft;
        size_t o = (size_t)r*D_ + d;
        g_hf[o] = h;
        g_a[o] = __float2half(h);
        g_mix[o] = 0.f;
    }
}

__global__ void rin_kernel(){
    int b = blockIdx.y;
    int d = blockIdx.x*256 + threadIdx.x;
    const float* hb = g_hf + (size_t)b*N_*D_;
    float s = 0.f;
    for (int n=0;n<N_;n++) s += hb[(size_t)n*D_ + d];
    g_rin[b*D_ + d] = s * (1.f/256.f);
}

__global__ void route_kernel(const float* __restrict__ wr){
    int b = blockIdx.x, tid = threadIdx.x;
    float acc[E_] = {0,0,0,0,0,0,0,0};
    for (int d=tid; d<D_; d+=256){
        float v = g_rin[b*D_ + d];
        #pragma unroll
        for (int e=0;e<E_;e++) acc[e] = fmaf(v, wr[d*E_ + e], acc[e]);
    }
    __shared__ float red[256];
    __shared__ float slog[E_];
    for (int e=0;e<E_;e++){
        red[tid] = acc[e];
        __syncthreads();
        for (int st=128; st>0; st>>=1){
            if (tid<st) red[tid] += red[tid+st];
            __syncthreads();
        }
        if (tid==0) slog[e] = red[0];
        __syncthreads();
    }
    if (tid==0){
        float p[E_];
        float mx = slog[0];
        for (int e=1;e<E_;e++) mx = fmaxf(mx, slog[e]);
        float ssum = 0.f;
        for (int e=0;e<E_;e++){ p[e] = expf(slog[e]-mx); ssum += p[e]; }
        for (int e=0;e<E_;e++){ p[e] /= ssum; g_probs[b*E_+e] = p[e]; }
        int i0 = 0;
        for (int e=1;e<E_;e++) if (p[e] > p[i0]) i0 = e;
        int i1 = (i0==0) ? 1 : 0;
        for (int e=0;e<E_;e++) if (e!=i0 && p[e] > p[i1]) i1 = e;
        float t = p[i0] + p[i1];
        for (int e=0;e<E_;e++){ g_combine[b*E_+e] = 0.f; g_slot[b*E_+e] = 255u; }
        g_combine[b*E_+i0] = p[i0]/t;  g_slot[b*E_+i0] = 0u;
        g_combine[b*E_+i1] = p[i1]/t;  g_slot[b*E_+i1] = 1u;
        g_top1[b] = i0;
    }
}

__global__ void aux_kernel(float* __restrict__ outp, int out_size){
    if (threadIdx.x != 0) return;
    float meanp[E_]; int cnt[E_];
    for (int e=0;e<E_;e++){ meanp[e]=0.f; cnt[e]=0; }
    for (int b=0;b<B_;b++){
        for (int e=0;e<E_;e++) meanp[e] += g_probs[b*E_+e];
        cnt[g_top1[b]]++;
    }
    float aux = 0.f;
    for (int e=0;e<E_;e++) aux += (meanp[e]*(1.f/B_)) * ((float)cnt[e]*(1.f/B_));
    aux *= (float)E_;
    if (out_size > BND) outp[BND] = aux;
}

__global__ void ew2_kernel(const float* __restrict__ x, const float* __restrict__ b_ada,
                           float* __restrict__ outp){
    int r = blockIdx.x, b = r >> 8, tid = threadIdx.x;
    float v[4];
    #pragma unroll
    for (int k=0;k<4;k++){
        int d = tid*4+k;
        float g = g_mod[b*6144 + 2*D_ + d] + b_ada[2*D_ + d];
        float x1 = x[(size_t)r*D_ + d] + g * g_mix[(size_t)r*D_ + d];
        outp[(size_t)r*D_ + d] = x1;
        v[k] = x1;
    }
    float s = v[0]+v[1]+v[2]+v[3];
    float q = v[0]*v[0]+v[1]*v[1]+v[2]*v[2]+v[3]*v[3];
    __shared__ float rs[256], rq[256];
    rs[tid]=s; rq[tid]=q; __syncthreads();
    for (int st=128; st>0; st>>=1){
        if (tid<st){ rs[tid]+=rs[tid+st]; rq[tid]+=rq[tid+st]; }
        __syncthreads();
    }
    float mu  = rs[0]*(1.f/1024.f);
    float var = rq[0]*(1.f/1024.f) - mu*mu;
    float rstd = rsqrtf(var + 1e-6f);
    #pragma unroll
    for (int k=0;k<4;k++){
        int d = tid*4+k;
        float sft = g_mod[b*6144 + 3*D_ + d] + b_ada[3*D_ + d];
        float scl = g_mod[b*6144 + 4*D_ + d] + b_ada[4*D_ + d];
        float h2 = (v[k]-mu)*rstd*(1.f+scl) + sft;
        g_a[(size_t)r*D_ + d] = __float2half(h2);
    }
}

// ---------------- launch ------------------------------------------------------
extern "C" void kernel_launch(void* const* d_in, const int* in_sizes, int n_in,
                              void* d_out, int out_size) {
    const float* x        = (const float*)d_in[0];
    const float* c        = (const float*)d_in[1];
    const float* w_ada    = (const float*)d_in[2];
    const float* b_ada    = (const float*)d_in[3];
    const float* w_router = (const float*)d_in[4];
    const float* tm_w1    = (const float*)d_in[5];
    const float* tm_b1    = (const float*)d_in[6];
    const float* tm_w2    = (const float*)d_in[7];
    const float* tm_b2    = (const float*)d_in[8];
    const float* cm_w1    = (const float*)d_in[9];
    const float* cm_b1    = (const float*)d_in[10];
    const float* cm_w2    = (const float*)d_in[11];
    const float* cm_b2    = (const float*)d_in[12];
    const float* mlp_w1   = (const float*)d_in[13];
    const float* mlp_b1   = (const float*)d_in[14];
    const float* mlp_w2   = (const float*)d_in[15];
    const float* mlp_b2   = (const float*)d_in[16];
    float* outp = (float*)d_out;

    static int attr_done = 0;
    if (!attr_done){
        cudaFuncSetAttribute(tgemm<T_TOK1>, cudaFuncAttributeMaxDynamicSharedMemorySize, SMEM_BYTES);
        cudaFuncSetAttribute(tgemm<T_TOK2>, cudaFuncAttributeMaxDynamicSharedMemorySize, SMEM_BYTES);
        cudaFuncSetAttribute(tgemm<T_CH1>,  cudaFuncAttributeMaxDynamicSharedMemorySize, SMEM_BYTES);
        cudaFuncSetAttribute(tgemm<T_CH2>,  cudaFuncAttributeMaxDynamicSharedMemorySize, SMEM_BYTES);
        cudaFuncSetAttribute(tgemm<T_MLP1>, cudaFuncAttributeMaxDynamicSharedMemorySize, SMEM_BYTES);
        cudaFuncSetAttribute(tgemm<T_MLP2>, cudaFuncAttributeMaxDynamicSharedMemorySize, SMEM_BYTES);
        attr_done = 1;
    }

    // adaLN modulation (SIMT fp32, K-split atomic into zeroed g_mod)
    zero_mod_kernel<<<384, 1024>>>();
    gemm_mod<<<dim3(48,1,8), 256>>>(c, w_ada);

    // weight transpose + fp16 convert:  W[K,N] fp32 -> Wt [N,K] fp16
    dim3 tb(32,8);
    __half* wp;
    cudaGetSymbolAddress((void**)&wp, g_w);
    tsplit<<<dim3(1024/32, 256/32, 4), tb>>>(tm_w1,  wp+OFF_TM1,  256, 1024);
    tsplit<<<dim3(256/32, 1024/32, 4), tb>>>(tm_w2,  wp+OFF_TM2,  1024, 256);
    tsplit<<<dim3(4096/32,1024/32, 4), tb>>>(cm_w1,  wp+OFF_CM1,  1024, 4096);
    tsplit<<<dim3(1024/32,4096/32, 4), tb>>>(cm_w2,  wp+OFF_CM2,  4096, 1024);
    tsplit<<<dim3(4096/32,1024/32, 1), tb>>>(mlp_w1, wp+OFF_MLP1, 1024, 4096);
    tsplit<<<dim3(1024/32,4096/32, 1), tb>>>(mlp_w2, wp+OFF_MLP2, 4096, 1024);

    // LN + modulate; fp16 convert; zero mix
    ew1_kernel<<<B_*N_, 256>>>(x, b_ada);
    // h^T fp16 for token experts
    tsplit_ht<<<dim3(32, 8, 64), tb>>>();

    // routing (fp32 — selection identical to reference)
    rin_kernel<<<dim3(4, B_), 256>>>();
    route_kernel<<<B_, 256>>>(w_router);
    aux_kernel<<<1, 32>>>(outp, out_size);

    // routed experts (fp16 tensor cores, gated per (sample, expert))
    tgemm<T_TOK1><<<dim3( 8, 8, B_*4), 256, SMEM_BYTES>>>(tm_b1, nullptr, nullptr);
    tgemm<T_CH1> <<<dim3(32, 2, B_*4), 256, SMEM_BYTES>>>(cm_b1, nullptr, nullptr);
    tgemm<T_TOK2><<<dim3( 2, 8, B_*4), 256, SMEM_BYTES>>>(tm_b2, nullptr, nullptr);
    tgemm<T_CH2> <<<dim3( 8, 2, B_*4), 256, SMEM_BYTES>>>(cm_b2, nullptr, nullptr);

    // residual + second LN/modulate (x1 staged in d_out)
    ew2_kernel<<<B_*N_, 256>>>(x, b_ada, outp);

    // dense MLP (fp16 tensor cores), second residual fused into MLP2 epilogue
    tgemm<T_MLP1><<<dim3(32, 128, 1), 256, SMEM_BYTES>>>(mlp_b1, nullptr, nullptr);
    tgemm<T_MLP2><<<dim3( 8, 128, 1), 256, SMEM_BYTES>>>(mlp_b2, b_ada, outp);
}

// round 8
// speedup vs baseline: 7.1766x; 1.0164x over previous
#include <cuda_runtime.h>
#include <cuda_fp16.h>
#include <math.h>
#include <cstdint>

// Problem dims
#define B_   64
#define N_   256
#define D_   1024
#define E_   8
#define BND  (B_*N_*D_)   // 16777216

// ---------------- weight-transpose offsets (elements) ------------------------
#define OFF_TM1  0u
#define OFF_TM2  1048576u
#define OFF_CM1  2097152u
#define OFF_CM2  18874368u
#define OFF_MLP1 35651584u
#define OFF_MLP2 39845888u
#define WT_TOTAL 44040192u

// ---------------- device scratch (allocation-free: __device__ globals) ------
__device__ float g_hf[BND];                 // fp32 h (router + transpose source)
__device__ float g_mix[BND];                // mixer accumulation
__device__ __half g_a[BND];                 // h / h2 (fp16)  [b][n][d]
__device__ __half g_t[BND];                 // h^T (fp16)     [b][d][n]
__device__ __half g_e[134217728];           // hidden (expert slots / MLP)
__device__ __half g_w[WT_TOTAL];            // transposed fp16 weights [N][K]
__device__ float g_mod[B_*6144];
__device__ float g_rin[B_*D_];
__device__ float g_probs[B_*E_];
__device__ float g_combine[B_*E_];
__device__ int   g_top1[B_];
__device__ unsigned char g_slot[B_*E_];

// ---------------- math helpers ----------------------------------------------
__device__ __forceinline__ float gelu_f(float x){
    const float c0 = 0.7978845608028654f;
    float x3 = x*x*x;
    float t = tanhf(c0*(x + 0.044715f*x3));
    return 0.5f*x*(1.0f+t);
}
__device__ __forceinline__ float silu_f(float x){ return x / (1.0f + __expf(-x)); }

// ---------------- PTX helpers ------------------------------------------------
__device__ __forceinline__ uint32_t smem_u32(const void* p){
    uint32_t a;
    asm("{ .reg .u64 t; cvta.to.shared.u64 t, %1; cvt.u32.u64 %0, t; }" : "=r"(a) : "l"(p));
    return a;
}
__device__ __forceinline__ void cpa16(uint32_t dst, const void* src){
    asm volatile("cp.async.cg.shared.global [%0], [%1], 16;" :: "r"(dst), "l"(src));
}
#define CP_COMMIT()  asm volatile("cp.async.commit_group;" ::: "memory")
#define CP_WAIT(n)   asm volatile("cp.async.wait_group %0;" :: "n"(n) : "memory")

// fp16 m16n8k16 tensor-core MMA, fp32 accum (baseline PTX)
#define MMA16816(c, a, b) \
    asm volatile("mma.sync.aligned.m16n8k16.row.col.f32.f16.f16.f32 " \
        "{%0,%1,%2,%3}, {%4,%5,%6,%7}, {%8,%9}, {%0,%1,%2,%3};" \
        : "+f"((c)[0]), "+f"((c)[1]), "+f"((c)[2]), "+f"((c)[3]) \
        : "r"((a)[0]), "r"((a)[1]), "r"((a)[2]), "r"((a)[3]), "r"((b)[0]), "r"((b)[1]))

// ldmatrix x4 (baseline PTX, sm_75+)
#define LDSM4(r0,r1,r2,r3,addr) \
    asm volatile("ldmatrix.sync.aligned.m8n8.x4.shared.b16 {%0,%1,%2,%3}, [%4];" \
        : "=r"(r0), "=r"(r1), "=r"(r2), "=r"(r3) : "r"(addr))

// ---------------- tensor GEMM (fp16 single pass) ------------------------------
// 128x128 block tile, BK=64, 256 threads (8 warps, each 32m x 64n), 2 CTAs/SM.
// 3-stage cp.async pipeline (prefetch depth 2), ONE barrier per chunk.
// smem tiles: 128 rows x 64 fp16, row pitch 144B (conflict-free for ldmatrix).
enum { T_TOK1=0, T_TOK2=1, T_CH1=2, T_CH2=3, T_MLP1=4, T_MLP2=5 };

#define TILE_B    18432           // 128 * 144
#define STAGE_B   36864           // 2 tiles (A, B)
#define NSTAGE    3
#define SMEM_BYTES 110592         // 3 stages

__device__ __forceinline__ void ld_chunk(uint32_t sb, int s,
    const __half* A, const __half* Bv,
    int m0, int n0, int k0, int ldk, int tid)
{
    #pragma unroll
    for (int t=0;t<4;t++){
        int j = tid + t*256;
        int r = j >> 3, c16 = j & 7;
        uint32_t d0 = sb + (uint32_t)s*STAGE_B + r*144 + c16*16;
        cpa16(d0,          A  + (size_t)(m0 + r)*ldk + k0 + c16*8);
        cpa16(d0 + TILE_B, Bv + (size_t)(n0 + r)*ldk + k0 + c16*8);
    }
    CP_COMMIT();
}

template<int MODE>
__global__ __launch_bounds__(256,2) void tgemm(const float* __restrict__ bias,
                                               const float* __restrict__ b_ada,
                                               float* __restrict__ outp)
{
    constexpr int Ktot = (MODE==T_TOK1)?256 : (MODE==T_CH2||MODE==T_MLP2)?4096 : 1024;
    constexpr int NC   = Ktot/64;

    const int tid = threadIdx.x;
    const int wid = tid >> 5, lid = tid & 31;
    const int m0 = blockIdx.y*128, n0 = blockIdx.x*128;
    const int warpM = wid & 3, warpN = wid >> 2;
    const int g = lid >> 2, q = lid & 3;

    const __half *A, *Bv;
    const float* be = bias;
    float wgt = 0.f; float* mixp = nullptr;
    __half* Cp = nullptr;
    constexpr int ldc = (MODE==T_TOK1)?1024 : (MODE==T_CH1||MODE==T_MLP1)?4096 : 1;

    if constexpr (MODE==T_TOK1||MODE==T_TOK2||MODE==T_CH1||MODE==T_CH2){
        int b = blockIdx.z >> 2, e = blockIdx.z & 3;
        int eg = (MODE==T_CH1||MODE==T_CH2) ? 4+e : e;
        unsigned char sl = g_slot[b*E_ + eg];
        if (sl == 255u) return;
        size_t so = (size_t)(b*2 + sl) * 1048576u;
        if constexpr (MODE==T_TOK1){
            A  = g_t + (size_t)b*262144;
            Bv = g_w + OFF_TM1 + (size_t)e*262144;
            be = bias + e*1024; Cp = g_e + so;
        } else if constexpr (MODE==T_TOK2){
            A  = g_e + so;
            Bv = g_w + OFF_TM2 + (size_t)e*262144;
            be = bias + e*256; mixp = g_mix + (size_t)b*262144; wgt = g_combine[b*E_ + eg];
        } else if constexpr (MODE==T_CH1){
            A  = g_a + (size_t)b*262144;
            Bv = g_w + OFF_CM1 + (size_t)e*4194304;
            be = bias + e*4096; Cp = g_e + so;
        } else {
            A  = g_e + so;
            Bv = g_w + OFF_CM2 + (size_t)e*4194304;
            be = bias + e*1024; mixp = g_mix + (size_t)b*262144; wgt = g_combine[b*E_ + eg];
        }
    } else if constexpr (MODE==T_MLP1){
        A = g_a; Bv = g_w + OFF_MLP1; Cp = g_e;
    } else {
        A = g_e; Bv = g_w + OFF_MLP2;
    }

    extern __shared__ char smem[];
    const uint32_t sbase = smem_u32(smem);

    // per-thread ldmatrix base addresses (stage 0, kk=0)
    const uint32_t aA = sbase + (uint32_t)(warpM*32 + (lid & 15))*144 + ((lid >> 4)*8)*2;
    const uint32_t aB = sbase + TILE_B
                      + (uint32_t)(warpN*64 + ((lid >> 4)*8) + (lid & 7))*144
                      + (((lid >> 3) & 1)*8)*2;

    float acc[2][8][4];
    #pragma unroll
    for (int i=0;i<2;i++)
        #pragma unroll
        for (int j=0;j<8;j++)
            #pragma unroll
            for (int k=0;k<4;k++) acc[i][j][k] = 0.f;

    // prologue: prefetch chunks 0 and 1
    ld_chunk(sbase, 0, A, Bv, m0, n0, 0, Ktot, tid);
    if (NC > 1) ld_chunk(sbase, 1, A, Bv, m0, n0, 64, Ktot, tid);

    int stage = 0;
    for (int c = 0; c < NC; c++){
        // wait for chunk c's group (outstanding after wait: <=1 = chunk c+1)
        if (c + 1 < NC) { CP_WAIT(1); } else { CP_WAIT(0); }
        __syncthreads();   // single barrier per chunk:
                           //  - makes chunk c's data visible to all warps
                           //  - guarantees reads of stage (c-1)%3 are done, so the
                           //    issue below (into that same stage) is race-free
        if (c + 2 < NC){
            int ws = stage + 2; if (ws >= NSTAGE) ws -= NSTAGE;
            ld_chunk(sbase, ws, A, Bv, m0, n0, (c+2)*64, Ktot, tid);
        }

        const uint32_t sOff = (uint32_t)stage*STAGE_B;

        #pragma unroll
        for (int kk = 0; kk < 64; kk += 16){
            uint32_t af[2][4];
            #pragma unroll
            for (int ma=0;ma<2;ma++){
                uint32_t base = aA + sOff + ma*2304 + kk*2;
                LDSM4(af[ma][0], af[ma][1], af[ma][2], af[ma][3], base);
            }
            uint32_t bf[8][2];
            #pragma unroll
            for (int p=0;p<4;p++){
                uint32_t base = aB + sOff + p*2304 + kk*2;
                LDSM4(bf[2*p][0], bf[2*p][1], bf[2*p+1][0], bf[2*p+1][1], base);
            }
            #pragma unroll
            for (int ma=0;ma<2;ma++)
                #pragma unroll
                for (int nb=0;nb<8;nb++)
                    MMA16816(acc[ma][nb], af[ma], bf[nb]);
        }
        if (++stage == NSTAGE) stage = 0;
    }

    // ---- epilogue ----
    #pragma unroll
    for (int ma=0;ma<2;ma++){
        #pragma unroll
        for (int nb=0;nb<8;nb++){
            int r0 = m0 + warpM*32 + ma*16 + g;
            int nc = n0 + warpN*64 + nb*8 + q*2;
            #pragma unroll
            for (int hv=0;hv<2;hv++){            // hv=0: rows r0, hv=1: rows r0+8
                int m = r0 + hv*8;
                #pragma unroll
                for (int jj=0;jj<2;jj++){
                    int n = nc + jj;
                    float v = acc[ma][nb][hv*2+jj] + be[n];
                    if constexpr (MODE==T_TOK1 || MODE==T_CH1 || MODE==T_MLP1){
                        Cp[(size_t)m*ldc + n] = __float2half(gelu_f(v));
                    } else if constexpr (MODE==T_TOK2){
                        atomicAdd(&mixp[(size_t)n*D_ + m], wgt * v);   // m=d, n=token
                    } else if constexpr (MODE==T_CH2){
                        atomicAdd(&mixp[(size_t)m*D_ + n], wgt * v);
                    } else { // MLP2
                        int bb = m >> 8;
                        float gml = g_mod[bb*6144 + 5120 + n] + b_ada[5120 + n];
                        size_t o = (size_t)m*D_ + n;
                        outp[o] = outp[o] + gml * v;
                    }
                }
            }
        }
    }
}

// ---------------- transpose + fp16 convert kernels ----------------------------
__global__ void tsplit(const float* __restrict__ src, __half* __restrict__ dst,
                       int R, int C){
    int z = blockIdx.z;
    src += (size_t)z*R*C; dst += (size_t)z*R*C;
    __shared__ float t[32][33];
    int r0 = blockIdx.y*32, c0 = blockIdx.x*32;
    int tx = threadIdx.x, ty = threadIdx.y;
    #pragma unroll
    for (int i = ty; i < 32; i += 8)
        t[i][tx] = src[(size_t)(r0+i)*C + c0 + tx];
    __syncthreads();
    #pragma unroll
    for (int i = ty; i < 32; i += 8)
        dst[(size_t)(c0+i)*R + r0 + tx] = __float2half(t[tx][i]);
}

__global__ void tsplit_ht(){   // g_hf [b][n][d] -> g_t [b][d][n]
    int z = blockIdx.z;
    const float* src = g_hf + (size_t)z*262144;
    __half* dst = g_t + (size_t)z*262144;
    __shared__ float t[32][33];
    int r0 = blockIdx.y*32, c0 = blockIdx.x*32;   // r=n (256), c=d (1024)
    int tx = threadIdx.x, ty = threadIdx.y;
    #pragma unroll
    for (int i = ty; i < 32; i += 8)
        t[i][tx] = src[(size_t)(r0+i)*1024 + c0 + tx];
    __syncthreads();
    #pragma unroll
    for (int i = ty; i < 32; i += 8)
        dst[(size_t)(c0+i)*256 + r0 + tx] = __float2half(t[tx][i]);
}

// ---------------- adaLN SIMT GEMM (small) -------------------------------------
__global__ void zero_mod_kernel(){
    int i = blockIdx.x*1024 + threadIdx.x;
    g_mod[i] = 0.f;
}

__global__ __launch_bounds__(256) void gemm_mod(const float* __restrict__ Aext,
                                                const float* __restrict__ W){
    const int tid = threadIdx.x;
    const int n0 = blockIdx.x * 128;
    const int kbeg = blockIdx.z * 128, kend = kbeg + 128;
    __shared__ __align__(16) float As[8][132];
    __shared__ __align__(16) float Bs[8][132];
    float acc[8][8];
    #pragma unroll
    for (int i=0;i<8;i++) for (int j=0;j<8;j++) acc[i][j] = 0.f;
    const int tx = tid & 15, ty = tid >> 4;
    for (int k0 = kbeg; k0 < kend; k0 += 8){
        #pragma unroll
        for (int j=0;j<4;j++){
            int i = tid + j*256;
            int m = i >> 3, kk = i & 7;
            As[kk][m] = (m < B_) ? silu_f(Aext[m*1024 + k0 + kk]) : 0.f;
        }
        #pragma unroll
        for (int j=0;j<4;j++){
            int i = tid + j*256;
            int kk = i >> 7, n = i & 127;
            Bs[kk][n] = W[(size_t)(k0+kk)*6144 + n0 + n];
        }
        __syncthreads();
        #pragma unroll
        for (int kk=0; kk<8; kk++){
            float a[8], b[8];
            #pragma unroll
            for (int i=0;i<8;i++) a[i] = As[kk][ty*8+i];
            #pragma unroll
            for (int j=0;j<8;j++) b[j] = Bs[kk][tx*8+j];
            #pragma unroll
            for (int i=0;i<8;i++)
                #pragma unroll
                for (int j=0;j<8;j++) acc[i][j] = fmaf(a[i], b[j], acc[i][j]);
        }
        __syncthreads();
    }
    #pragma unroll
    for (int i=0;i<8;i++){
        int m = ty*8 + i;
        if (m >= B_) continue;
        #pragma unroll
        for (int j=0;j<8;j++){
            int n = n0 + tx*8 + j;
            atomicAdd(&g_mod[m*6144 + n], acc[i][j]);
        }
    }
}

// ---------------- elementwise / routing kernels ------------------------------
__global__ void ew1_kernel(const float* __restrict__ x, const float* __restrict__ b_ada){
    int r = blockIdx.x, b = r >> 8, tid = threadIdx.x;
    const float* xr = x + (size_t)r*D_;
    float v[4];
    #pragma unroll
    for (int k=0;k<4;k++) v[k] = xr[tid*4+k];
    float s = v[0]+v[1]+v[2]+v[3];
    float q = v[0]*v[0]+v[1]*v[1]+v[2]*v[2]+v[3]*v[3];
    __shared__ float rs[256], rq[256];
    rs[tid]=s; rq[tid]=q; __syncthreads();
    for (int st=128; st>0; st>>=1){
        if (tid<st){ rs[tid]+=rs[tid+st]; rq[tid]+=rq[tid+st]; }
        __syncthreads();
    }
    float mu  = rs[0]*(1.f/1024.f);
    float var = rq[0]*(1.f/1024.f) - mu*mu;
    float rstd = rsqrtf(var + 1e-6f);
    #pragma unroll
    for (int k=0;k<4;k++){
        int d = tid*4+k;
        float sft = g_mod[b*6144 + d]      + b_ada[d];
        float scl = g_mod[b*6144 + D_ + d] + b_ada[D_ + d];
        float h = (v[k]-mu)*rstd*(1.f+scl) + sft;
        size_t o = (size_t)r*D_ + d;
        g_hf[o] = h;
        g_a[o] = __float2half(h);
        g_mix[o] = 0.f;
    }
}

__global__ void rin_kernel(){
    int b = blockIdx.y;
    int d = blockIdx.x*256 + threadIdx.x;
    const float* hb = g_hf + (size_t)b*N_*D_;
    float s = 0.f;
    for (int n=0;n<N_;n++) s += hb[(size_t)n*D_ + d];
    g_rin[b*D_ + d] = s * (1.f/256.f);
}

__global__ void route_kernel(const float* __restrict__ wr){
    int b = blockIdx.x, tid = threadIdx.x;
    float acc[E_] = {0,0,0,0,0,0,0,0};
    for (int d=tid; d<D_; d+=256){
        float v = g_rin[b*D_ + d];
        #pragma unroll
        for (int e=0;e<E_;e++) acc[e] = fmaf(v, wr[d*E_ + e], acc[e]);
    }
    __shared__ float red[256];
    __shared__ float slog[E_];
    for (int e=0;e<E_;e++){
        red[tid] = acc[e];
        __syncthreads();
        for (int st=128; st>0; st>>=1){
            if (tid<st) red[tid] += red[tid+st];
            __syncthreads();
        }
        if (tid==0) slog[e] = red[0];
        __syncthreads();
    }
    if (tid==0){
        float p[E_];
        float mx = slog[0];
        for (int e=1;e<E_;e++) mx = fmaxf(mx, slog[e]);
        float ssum = 0.f;
        for (int e=0;e<E_;e++){ p[e] = expf(slog[e]-mx); ssum += p[e]; }
        for (int e=0;e<E_;e++){ p[e] /= ssum; g_probs[b*E_+e] = p[e]; }
        int i0 = 0;
        for (int e=1;e<E_;e++) if (p[e] > p[i0]) i0 = e;
        int i1 = (i0==0) ? 1 : 0;
        for (int e=0;e<E_;e++) if (e!=i0 && p[e] > p[i1]) i1 = e;
        float t = p[i0] + p[i1];
        for (int e=0;e<E_;e++){ g_combine[b*E_+e] = 0.f; g_slot[b*E_+e] = 255u; }
        g_combine[b*E_+i0] = p[i0]/t;  g_slot[b*E_+i0] = 0u;
        g_combine[b*E_+i1] = p[i1]/t;  g_slot[b*E_+i1] = 1u;
        g_top1[b] = i0;
    }
}

__global__ void aux_kernel(float* __restrict__ outp, int out_size){
    if (threadIdx.x != 0) return;
    float meanp[E_]; int cnt[E_];
    for (int e=0;e<E_;e++){ meanp[e]=0.f; cnt[e]=0; }
    for (int b=0;b<B_;b++){
        for (int e=0;e<E_;e++) meanp[e] += g_probs[b*E_+e];
        cnt[g_top1[b]]++;
    }
    float aux = 0.f;
    for (int e=0;e<E_;e++) aux += (meanp[e]*(1.f/B_)) * ((float)cnt[e]*(1.f/B_));
    aux *= (float)E_;
    if (out_size > BND) outp[BND] = aux;
}

__global__ void ew2_kernel(const float* __restrict__ x, const float* __restrict__ b_ada,
                           float* __restrict__ outp){
    int r = blockIdx.x, b = r >> 8, tid = threadIdx.x;
    float v[4];
    #pragma unroll
    for (int k=0;k<4;k++){
        int d = tid*4+k;
        float g = g_mod[b*6144 + 2*D_ + d] + b_ada[2*D_ + d];
        float x1 = x[(size_t)r*D_ + d] + g * g_mix[(size_t)r*D_ + d];
        outp[(size_t)r*D_ + d] = x1;
        v[k] = x1;
    }
    float s = v[0]+v[1]+v[2]+v[3];
    float q = v[0]*v[0]+v[1]*v[1]+v[2]*v[2]+v[3]*v[3];
    __shared__ float rs[256], rq[256];
    rs[tid]=s; rq[tid]=q; __syncthreads();
    for (int st=128; st>0; st>>=1){
        if (tid<st){ rs[tid]+=rs[tid+st]; rq[tid]+=rq[tid+st]; }
        __syncthreads();
    }
    float mu  = rs[0]*(1.f/1024.f);
    float var = rq[0]*(1.f/1024.f) - mu*mu;
    float rstd = rsqrtf(var + 1e-6f);
    #pragma unroll
    for (int k=0;k<4;k++){
        int d = tid*4+k;
        float sft = g_mod[b*6144 + 3*D_ + d] + b_ada[3*D_ + d];
        float scl = g_mod[b*6144 + 4*D_ + d] + b_ada[4*D_ + d];
        float h2 = (v[k]-mu)*rstd*(1.f+scl) + sft;
        g_a[(size_t)r*D_ + d] = __float2half(h2);
    }
}

// ---------------- launch ------------------------------------------------------
extern "C" void kernel_launch(void* const* d_in, const int* in_sizes, int n_in,
                              void* d_out, int out_size) {
    const float* x        = (const float*)d_in[0];
    const float* c        = (const float*)d_in[1];
    const float* w_ada    = (const float*)d_in[2];
    const float* b_ada    = (const float*)d_in[3];
    const float* w_router = (const float*)d_in[4];
    const float* tm_w1    = (const float*)d_in[5];
    const float* tm_b1    = (const float*)d_in[6];
    const float* tm_w2    = (const float*)d_in[7];
    const float* tm_b2    = (const float*)d_in[8];
    const float* cm_w1    = (const float*)d_in[9];
    const float* cm_b1    = (const float*)d_in[10];
    const float* cm_w2    = (const float*)d_in[11];
    const float* cm_b2    = (const float*)d_in[12];
    const float* mlp_w1   = (const float*)d_in[13];
    const float* mlp_b1   = (const float*)d_in[14];
    const float* mlp_w2   = (const float*)d_in[15];
    const float* mlp_b2   = (const float*)d_in[16];
    float* outp = (float*)d_out;

    static int attr_done = 0;
    if (!attr_done){
        cudaFuncSetAttribute(tgemm<T_TOK1>, cudaFuncAttributeMaxDynamicSharedMemorySize, SMEM_BYTES);
        cudaFuncSetAttribute(tgemm<T_TOK2>, cudaFuncAttributeMaxDynamicSharedMemorySize, SMEM_BYTES);
        cudaFuncSetAttribute(tgemm<T_CH1>,  cudaFuncAttributeMaxDynamicSharedMemorySize, SMEM_BYTES);
        cudaFuncSetAttribute(tgemm<T_CH2>,  cudaFuncAttributeMaxDynamicSharedMemorySize, SMEM_BYTES);
        cudaFuncSetAttribute(tgemm<T_MLP1>, cudaFuncAttributeMaxDynamicSharedMemorySize, SMEM_BYTES);
        cudaFuncSetAttribute(tgemm<T_MLP2>, cudaFuncAttributeMaxDynamicSharedMemorySize, SMEM_BYTES);
        attr_done = 1;
    }

    // adaLN modulation (SIMT fp32, K-split atomic into zeroed g_mod)
    zero_mod_kernel<<<384, 1024>>>();
    gemm_mod<<<dim3(48,1,8), 256>>>(c, w_ada);

    // weight transpose + fp16 convert:  W[K,N] fp32 -> Wt [N,K] fp16
    dim3 tb(32,8);
    __half* wp;
    cudaGetSymbolAddress((void**)&wp, g_w);
    tsplit<<<dim3(1024/32, 256/32, 4), tb>>>(tm_w1,  wp+OFF_TM1,  256, 1024);
    tsplit<<<dim3(256/32, 1024/32, 4), tb>>>(tm_w2,  wp+OFF_TM2,  1024, 256);
    tsplit<<<dim3(4096/32,1024/32, 4), tb>>>(cm_w1,  wp+OFF_CM1,  1024, 4096);
    tsplit<<<dim3(1024/32,4096/32, 4), tb>>>(cm_w2,  wp+OFF_CM2,  4096, 1024);
    tsplit<<<dim3(4096/32,1024/32, 1), tb>>>(mlp_w1, wp+OFF_MLP1, 1024, 4096);
    tsplit<<<dim3(1024/32,4096/32, 1), tb>>>(mlp_w2, wp+OFF_MLP2, 4096, 1024);

    // LN + modulate; fp16 convert; zero mix
    ew1_kernel<<<B_*N_, 256>>>(x, b_ada);
    // h^T fp16 for token experts
    tsplit_ht<<<dim3(32, 8, 64), tb>>>();

    // routing (fp32 — selection identical to reference)
    rin_kernel<<<dim3(4, B_), 256>>>();
    route_kernel<<<B_, 256>>>(w_router);
    aux_kernel<<<1, 32>>>(outp, out_size);

    // routed experts (fp16 tensor cores, gated per (sample, expert))
    tgemm<T_TOK1><<<dim3( 8, 8, B_*4), 256, SMEM_BYTES>>>(tm_b1, nullptr, nullptr);
    tgemm<T_CH1> <<<dim3(32, 2, B_*4), 256, SMEM_BYTES>>>(cm_b1, nullptr, nullptr);
    tgemm<T_TOK2><<<dim3( 2, 8, B_*4), 256, SMEM_BYTES>>>(tm_b2, nullptr, nullptr);
    tgemm<T_CH2> <<<dim3( 8, 2, B_*4), 256, SMEM_BYTES>>>(cm_b2, nullptr, nullptr);

    // residual + second LN/modulate (x1 staged in d_out)
    ew2_kernel<<<B_*N_, 256>>>(x, b_ada, outp);

    // dense MLP (fp16 tensor cores), second residual fused into MLP2 epilogue
    tgemm<T_MLP1><<<dim3(32, 128, 1), 256, SMEM_BYTES>>>(mlp_b1, nullptr, nullptr);
    tgemm<T_MLP2><<<dim3( 8, 128, 1), 256, SMEM_BYTES>>>(mlp_b2, b_ada, outp);
}